// round 5
// baseline (speedup 1.0000x reference)
#include <cuda_runtime.h>
#include <math.h>

#define BB 4
#define NN 32768
#define CC 256
#define HH 8
#define DD 32
#define GG 32
#define TOK 32                      // tokens per block tile
#define TPW (TOK / 8)               // tokens per warp for LN/softmax = 4
#define BLKS_PER_BATCH (NN / TOK)   // 1024
#define NBLK (BB * BLKS_PER_BATCH)  // 4096

// ---------------- device scratch (allocation-free rule) ---------------------
__device__ float g_slice_w[(size_t)BB * NN * HH * GG];        // [b][n][h][g]
__device__ float g_part_tok[(size_t)NBLK * HH * GG * DD];     // [blk][h*G+g][d]
__device__ float g_part_norm[(size_t)NBLK * HH * GG];         // [blk][h*G+g]
__device__ float g_tokens[(size_t)BB * HH * GG * DD];         // [b][h][g][d]

typedef unsigned long long u64;

__device__ __forceinline__ void fma2(u64& d, u64 a, u64 b) {
    asm("fma.rn.f32x2 %0, %1, %2, %0;" : "+l"(d) : "l"(a), "l"(b));
}
__device__ __forceinline__ float2 unpack2(u64 v) {
    float2 f;
    asm("mov.b64 {%0, %1}, %2;" : "=f"(f.x), "=f"(f.y) : "l"(v));
    return f;
}

// ---------------- FFMA2 GEMM: 32x256 tile @ 256x256 W -----------------------
// 256 threads. Warp w: token rows (w&3)*8..+8, column half (w>>2).
// Thread owns cols {lane + 128*half + 32*jj}, jj=0..3  (8 tok x 4 col tile).
// W staged in smem k-pair-interleaved [kkp][c][2], double buffered, KP=8.
// All s_in reads precede the final __syncthreads; writes follow -> s_out may
// alias s_in.
template<int KP>
__device__ __forceinline__ void gemm2(const float* __restrict__ s_in,
                                      const float* __restrict__ Wg,
                                      const float* __restrict__ bias,
                                      float* __restrict__ s_out,
                                      float* __restrict__ s_pan)
{
    const int tid  = threadIdx.x;
    const int lane = tid & 31;
    const int rowg = (tid >> 5) & 3;        // token group (4 groups of 8 rows)
    const int half = tid >> 7;              // column half
    const int c0   = lane + 128 * half;     // base column
    constexpr int NPAN  = CC / KP;
    constexpr int PAIRS = KP / 2;           // float2 staged per thread/panel
    constexpr int PANF  = KP * CC;

    u64 acc[8][4];
#pragma unroll
    for (int t = 0; t < 8; ++t)
#pragma unroll
        for (int j = 0; j < 4; ++j) acc[t][j] = 0ull;

    // stage panel 0
#pragma unroll
    for (int i = 0; i < PAIRS; ++i) {
        const int p = tid + i * 256;
        const int kkp = p >> 8, c = p & 255;
        float2 w = make_float2(Wg[(2 * kkp) * CC + c], Wg[(2 * kkp + 1) * CC + c]);
        *reinterpret_cast<float2*>(&s_pan[2 * p]) = w;
    }
    __syncthreads();

#pragma unroll 1
    for (int pan = 0; pan < NPAN; ++pan) {
        float2 nw[PAIRS];
        if (pan + 1 < NPAN) {
            const float* Wn = Wg + (pan + 1) * KP * CC;
#pragma unroll
            for (int i = 0; i < PAIRS; ++i) {
                const int p = tid + i * 256;
                const int kkp = p >> 8, c = p & 255;
                nw[i] = make_float2(Wn[(2 * kkp) * CC + c], Wn[(2 * kkp + 1) * CC + c]);
            }
        }
        const float* pb = s_pan + (pan & 1) * PANF;
        const int k0 = pan * KP;
#pragma unroll
        for (int kq = 0; kq < KP / 4; ++kq) {      // k-quad = 4 k values
            u64 b0[4], b1[4];
#pragma unroll
            for (int j = 0; j < 4; ++j) {
                b0[j] = *reinterpret_cast<const u64*>(
                    &pb[(2 * kq) * 512 + (c0 + 32 * j) * 2]);
                b1[j] = *reinterpret_cast<const u64*>(
                    &pb[(2 * kq + 1) * 512 + (c0 + 32 * j) * 2]);
            }
#pragma unroll
            for (int th = 0; th < 2; ++th) {       // 2 row sub-groups of 4
                ulonglong2 a[4];
#pragma unroll
                for (int t = 0; t < 4; ++t)
                    a[t] = *reinterpret_cast<const ulonglong2*>(
                        &s_in[(rowg * 8 + th * 4 + t) * CC + k0 + kq * 4]);
#pragma unroll
                for (int t = 0; t < 4; ++t) {
#pragma unroll
                    for (int j = 0; j < 4; ++j) fma2(acc[th * 4 + t][j], a[t].x, b0[j]);
#pragma unroll
                    for (int j = 0; j < 4; ++j) fma2(acc[th * 4 + t][j], a[t].y, b1[j]);
                }
            }
        }
        if (pan + 1 < NPAN) {
            float* pbn = s_pan + ((pan + 1) & 1) * PANF;
#pragma unroll
            for (int i = 0; i < PAIRS; ++i)
                *reinterpret_cast<float2*>(&pbn[2 * (tid + i * 256)]) = nw[i];
        }
        __syncthreads();
    }

    float br[4];
#pragma unroll
    for (int j = 0; j < 4; ++j) br[j] = bias[c0 + 32 * j];
#pragma unroll
    for (int t = 0; t < 8; ++t)
#pragma unroll
        for (int j = 0; j < 4; ++j) {
            const float2 f = unpack2(acc[t][j]);
            s_out[(rowg * 8 + t) * CC + c0 + 32 * j] = f.x + f.y + br[j];
        }
}

// layer norm in-place: warp tg handles rows tg*TPW..+TPW-1 of [TOK x 256]
__device__ __forceinline__ void ln_rows(float* __restrict__ s_t,
                                        const float* __restrict__ ln_g,
                                        const float* __restrict__ ln_b,
                                        int tg, int lane)
{
#pragma unroll
    for (int t = tg * TPW; t < tg * TPW + TPW; ++t) {
        float s = 0.f, s2 = 0.f;
#pragma unroll
        for (int c = lane; c < CC; c += 32) {
            const float v = s_t[t * CC + c];
            s += v; s2 += v * v;
        }
#pragma unroll
        for (int o = 16; o; o >>= 1) {
            s  += __shfl_xor_sync(0xffffffffu, s,  o);
            s2 += __shfl_xor_sync(0xffffffffu, s2, o);
        }
        const float mu   = s * (1.f / CC);
        const float var  = s2 * (1.f / CC) - mu * mu;
        const float rstd = rsqrtf(var + 1e-5f);
#pragma unroll
        for (int c = lane; c < CC; c += 32) {
            const float v = s_t[t * CC + c];
            s_t[t * CC + c] = (v - mu) * rstd * ln_g[c] + ln_b[c];
        }
    }
}

// ---------------- K1: LN + x_mid/fx_mid GEMMs + slice_w + partial tokens ----
__global__ void __launch_bounds__(256, 2)
k1_dispatch(const float* __restrict__ fx,
            const float* __restrict__ ln_g, const float* __restrict__ ln_b,
            const float* __restrict__ Wx,  const float* __restrict__ bx,
            const float* __restrict__ Wfx, const float* __restrict__ bfx,
            const float* __restrict__ Ws,  const float* __restrict__ bs,
            const float* __restrict__ tempp)
{
    extern __shared__ float sm[];
    float* s_A   = sm;                   // TOKx256  fx -> fx_norm -> fx_mid
    float* s_B   = sm + TOK * CC;        // TOKx256  x_mid -> slice_w
    float* s_pan = sm + 2 * TOK * CC;    // 2*8*256 = 4096
    float* s_Ws  = s_pan + 4096;         // 32*32
    float* s_bs  = s_Ws + DD * GG;       // 32

    const int tid  = threadIdx.x;
    const int tg   = tid >> 5;
    const int lane = tid & 31;
    const int batch = blockIdx.x / BLKS_PER_BATCH;
    const int n0    = (blockIdx.x % BLKS_PER_BATCH) * TOK;

    for (int i = tid; i < DD * GG; i += 256) s_Ws[i] = Ws[i];
    if (tid < GG) s_bs[tid] = bs[tid];

    const float* fxp = fx + ((size_t)batch * NN + n0) * CC;
    for (int i = tid * 4; i < TOK * CC; i += 1024)
        *reinterpret_cast<float4*>(&s_A[i]) = *reinterpret_cast<const float4*>(&fxp[i]);
    __syncthreads();

    ln_rows(s_A, ln_g, ln_b, tg, lane);
    __syncthreads();

    gemm2<8>(s_A, Wx, bx, s_B, s_pan);   // x_mid
    __syncthreads();

    // slice logits + softmax, warp tg owns rows tg*4..+3 of s_B; lane = g
    {
        float invt[HH];
#pragma unroll
        for (int h = 0; h < HH; ++h) invt[h] = 1.0f / tempp[h];
        const int g = lane;
        const float bsg = s_bs[g];
        float wsr[DD];
#pragma unroll
        for (int d = 0; d < DD; ++d) wsr[d] = s_Ws[d * GG + g];
        for (int i = 0; i < TPW * HH; ++i) {
            const int t = tg * TPW + (i >> 3);
            const int h = i & 7;
            float lg = bsg;
#pragma unroll
            for (int d = 0; d < DD; ++d)
                lg = fmaf(s_B[t * CC + h * DD + d], wsr[d], lg);
            lg *= invt[h];
            float m = lg;
#pragma unroll
            for (int o = 16; o; o >>= 1) m = fmaxf(m, __shfl_xor_sync(0xffffffffu, m, o));
            const float e = __expf(lg - m);
            float ssum = e;
#pragma unroll
            for (int o = 16; o; o >>= 1) ssum += __shfl_xor_sync(0xffffffffu, ssum, o);
            const float wv = e / ssum;
            __syncwarp();
            s_B[t * CC + h * GG + g] = wv;
            g_slice_w[(((size_t)batch * NN + n0 + t) * HH + h) * GG + g] = wv;
        }
    }
    __syncthreads();

    gemm2<8>(s_A, Wfx, bfx, s_A, s_pan);  // fx_mid, in-place
    __syncthreads();

    // accumulate slice_token partials: warp tg = head, lane = g
    {
        const int h = tg, g = lane;
        float accT[DD];
#pragma unroll
        for (int d = 0; d < DD; ++d) accT[d] = 0.f;
        float accN = 0.f;
        for (int t = 0; t < TOK; ++t) {
            const float wv = s_B[t * CC + h * GG + g];
            accN += wv;
#pragma unroll
            for (int d = 0; d < DD; ++d)
                accT[d] = fmaf(wv, s_A[t * CC + h * DD + d], accT[d]);
        }
        float* pt = g_part_tok + ((size_t)blockIdx.x * (HH * GG) + tid) * DD;
#pragma unroll
        for (int d = 0; d < DD; d += 4)
            *reinterpret_cast<float4*>(&pt[d]) =
                make_float4(accT[d], accT[d + 1], accT[d + 2], accT[d + 3]);
        g_part_norm[(size_t)blockIdx.x * (HH * GG) + tid] = accN;
    }
}

// ---------------- K2: reduce partials + attention + MLP  (tiny) -------------
__global__ void __launch_bounds__(1024)
k2_tokens(const float* __restrict__ Wq, const float* __restrict__ Wk,
          const float* __restrict__ Wv,
          const float* __restrict__ tln_g, const float* __restrict__ tln_b,
          const float* __restrict__ W1, const float* __restrict__ b1,
          const float* __restrict__ W2, const float* __restrict__ b2)
{
    const int b = blockIdx.x / HH;
    const int h = blockIdx.x % HH;
    const int tid = threadIdx.x;
    const int g = tid >> 5, d = tid & 31;

    __shared__ float s_st[GG][DD + 1];
    __shared__ float s_q[GG][DD + 1], s_k[GG][DD + 1], s_v[GG][DD + 1];
    __shared__ float s_attn[GG][GG + 1];
    __shared__ float s_h1[GG][4 * DD];
    __shared__ float s_norm[GG];

    float tsum = 0.f;
#pragma unroll 4
    for (int pb = 0; pb < BLKS_PER_BATCH; ++pb) {
        const size_t blk = (size_t)b * BLKS_PER_BATCH + pb;
        tsum += g_part_tok[(blk * (HH * GG) + h * GG + g) * DD + d];
    }
    if (tid < GG) {
        float ns = 0.f;
#pragma unroll 4
        for (int pb = 0; pb < BLKS_PER_BATCH; ++pb) {
            const size_t blk = (size_t)b * BLKS_PER_BATCH + pb;
            ns += g_part_norm[blk * (HH * GG) + h * GG + tid];
        }
        s_norm[tid] = ns;
    }
    __syncthreads();

    const float st = tsum / (s_norm[g] + 1e-5f);
    s_st[g][d] = st;
    __syncthreads();

    float q = 0.f, kk = 0.f, vv = 0.f;
#pragma unroll
    for (int dd2 = 0; dd2 < DD; ++dd2) {
        const float sv = s_st[g][dd2];
        q  = fmaf(sv, Wq[dd2 * DD + d], q);
        kk = fmaf(sv, Wk[dd2 * DD + d], kk);
        vv = fmaf(sv, Wv[dd2 * DD + d], vv);
    }
    s_q[g][d] = q; s_k[g][d] = kk; s_v[g][d] = vv;
    __syncthreads();

    {
        const int kidx = d;
        float lg = 0.f;
#pragma unroll
        for (int dd2 = 0; dd2 < DD; ++dd2)
            lg = fmaf(s_q[g][dd2], s_k[kidx][dd2], lg);
        lg *= 0.17677669529663687f;
        float m = lg;
#pragma unroll
        for (int o = 16; o; o >>= 1) m = fmaxf(m, __shfl_xor_sync(0xffffffffu, m, o));
        const float e = __expf(lg - m);
        float ssum = e;
#pragma unroll
        for (int o = 16; o; o >>= 1) ssum += __shfl_xor_sync(0xffffffffu, ssum, o);
        s_attn[g][kidx] = e / ssum;
    }
    __syncthreads();

    float ot = st;
#pragma unroll
    for (int kidx = 0; kidx < GG; ++kidx)
        ot = fmaf(s_attn[g][kidx], s_v[kidx][d], ot);

    float s1 = ot, s2o = ot * ot;
#pragma unroll
    for (int o = 16; o; o >>= 1) {
        s1  += __shfl_xor_sync(0xffffffffu, s1,  o);
        s2o += __shfl_xor_sync(0xffffffffu, s2o, o);
    }
    const float mu   = s1 * (1.f / DD);
    const float var  = s2o * (1.f / DD) - mu * mu;
    const float rstd = rsqrtf(var + 1e-5f);
    const float hn = (ot - mu) * rstd * tln_g[d] + tln_b[d];
    __syncthreads();
    s_st[g][d] = hn;
    __syncthreads();

#pragma unroll
    for (int jj = 0; jj < 4; ++jj) {
        const int j = d + 32 * jj;
        float a = b1[j];
#pragma unroll
        for (int dd2 = 0; dd2 < DD; ++dd2)
            a = fmaf(s_st[g][dd2], W1[dd2 * (4 * DD) + j], a);
        a = 0.5f * a * (1.0f + erff(a * 0.70710678118654752f));
        s_h1[g][j] = a;
    }
    __syncthreads();

    float tk = b2[d];
#pragma unroll
    for (int j = 0; j < 4 * DD; ++j)
        tk = fmaf(s_h1[g][j], W2[j * DD + d], tk);
    tk += ot;
    g_tokens[(((size_t)b * HH + h) * GG + g) * DD + d] = tk;
}

// ---------------- K3: LN, combine, Wo GEMM + residual -----------------------
__global__ void __launch_bounds__(256, 2)
k3_combine(const float* __restrict__ fx,
           const float* __restrict__ ln_g, const float* __restrict__ ln_b,
           const float* __restrict__ Wo,  const float* __restrict__ bo,
           float* __restrict__ out)
{
    extern __shared__ float sm[];
    float* s_A   = sm;                   // fx -> fx_norm
    float* s_B   = sm + TOK * CC;        // slice_w; later overlaid as W panels
    float* s_C   = sm + 2 * TOK * CC;    // out_x -> Wo result (in place)

    const int tid  = threadIdx.x;
    const int tg   = tid >> 5;
    const int lane = tid & 31;
    const int batch = blockIdx.x / BLKS_PER_BATCH;
    const int n0    = (blockIdx.x % BLKS_PER_BATCH) * TOK;

    const float* fxp = fx + ((size_t)batch * NN + n0) * CC;
    for (int i = tid * 4; i < TOK * CC; i += 1024)
        *reinterpret_cast<float4*>(&s_A[i]) = *reinterpret_cast<const float4*>(&fxp[i]);
    const float* swp = g_slice_w + ((size_t)batch * NN + n0) * (HH * GG);
    for (int i = tid * 4; i < TOK * (HH * GG); i += 1024)
        *reinterpret_cast<float4*>(&s_B[i]) = *reinterpret_cast<const float4*>(&swp[i]);

    // tokens for head h=tg, component d=lane, all g: registers
    float tokr[GG];
#pragma unroll
    for (int g = 0; g < GG; ++g)
        tokr[g] = g_tokens[(((size_t)batch * HH + tg) * GG + g) * DD + lane];
    __syncthreads();

    ln_rows(s_A, ln_g, ln_b, tg, lane);

    // out_x: warp tg = head, lane = d
    for (int t = 0; t < TOK; ++t) {
        float a = 0.f;
#pragma unroll
        for (int g = 0; g < GG; ++g)
            a = fmaf(tokr[g], s_B[t * CC + tg * GG + g], a);
        s_C[t * CC + tg * DD + lane] = a;
    }
    __syncthreads();   // slice_w dead after this point -> s_B becomes panel buf

    gemm2<8>(s_C, Wo, bo, s_C, s_B);   // in-place
    __syncthreads();

    float* op = out + ((size_t)batch * NN + n0) * CC;
    for (int i = tid * 4; i < TOK * CC; i += 1024) {
        float4 c4 = *reinterpret_cast<float4*>(&s_C[i]);
        const float4 a4 = *reinterpret_cast<const float4*>(&s_A[i]);
        c4.x += a4.x; c4.y += a4.y; c4.z += a4.z; c4.w += a4.w;
        *reinterpret_cast<float4*>(&op[i]) = c4;
    }
}

// ---------------- launch -----------------------------------------------------
extern "C" void kernel_launch(void* const* d_in, const int* in_sizes, int n_in,
                              void* d_out, int out_size)
{
    const float* fx    = (const float*)d_in[0];
    const float* ln_g  = (const float*)d_in[1];
    const float* ln_b  = (const float*)d_in[2];
    const float* Wx    = (const float*)d_in[3];
    const float* bx    = (const float*)d_in[4];
    const float* Wfx   = (const float*)d_in[5];
    const float* bfx   = (const float*)d_in[6];
    const float* Ws    = (const float*)d_in[7];
    const float* bs    = (const float*)d_in[8];
    const float* tempp = (const float*)d_in[9];
    const float* Wq    = (const float*)d_in[10];
    const float* Wk    = (const float*)d_in[11];
    const float* Wv    = (const float*)d_in[12];
    const float* tln_g = (const float*)d_in[13];
    const float* tln_b = (const float*)d_in[14];
    const float* W1    = (const float*)d_in[15];
    const float* b1    = (const float*)d_in[16];
    const float* W2    = (const float*)d_in[17];
    const float* b2    = (const float*)d_in[18];
    const float* Wo    = (const float*)d_in[19];
    const float* bo    = (const float*)d_in[20];
    float* out = (float*)d_out;

    const int smem1 = (2 * TOK * CC + 4096 + DD * GG + GG) * (int)sizeof(float); // ~84KB
    const int smem3 = (3 * TOK * CC) * (int)sizeof(float);                       // 96KB
    static int s_init = 0;
    if (!s_init) {
        cudaFuncSetAttribute(k1_dispatch, cudaFuncAttributeMaxDynamicSharedMemorySize, smem1);
        cudaFuncSetAttribute(k3_combine,  cudaFuncAttributeMaxDynamicSharedMemorySize, smem3);
        s_init = 1;
    }

    k1_dispatch<<<NBLK, 256, smem1>>>(fx, ln_g, ln_b, Wx, bx, Wfx, bfx, Ws, bs, tempp);
    k2_tokens<<<BB * HH, 1024>>>(Wq, Wk, Wv, tln_g, tln_b, W1, b1, W2, b2);
    k3_combine<<<NBLK, 256, smem3>>>(fx, ln_g, ln_b, Wo, bo, out);
}

// round 9
// speedup vs baseline: 1.5430x; 1.5430x over previous
#include <cuda_runtime.h>
#include <cuda_bf16.h>
#include <math.h>
#include <cstdint>

#define BB 4
#define NN 32768
#define CC 256
#define HH 8
#define DD 32
#define GG 32
#define TOK1 64
#define BLKS1 (NN / TOK1)            // 512
#define NBLK1 (BB * BLKS1)           // 2048
#define TOK3 128
#define BLKS3 (NN / TOK3)            // 256
#define NBLK3 (BB * BLKS3)           // 1024

typedef unsigned int u32;
typedef unsigned short u16;

// ---------------- device scratch ---------------------------------------------
__device__ u32   g_Bxs_hi[32768], g_Bxs_lo[32768];   // WxWs frag images
__device__ u32   g_Bfx_hi[32768], g_Bfx_lo[32768];   // Wfx frag images
__device__ float g_blog[256];
__device__ u16   g_w_hi[(size_t)BB * NN * 256];      // slice_w bf16 hi [b][n][hg]
__device__ u16   g_w_lo[(size_t)BB * NN * 256];
__device__ float g_part_tok[(size_t)NBLK1 * 256 * DD];
__device__ float g_part_norm[(size_t)NBLK1 * 256];
__device__ u32   g_Wt_hi[(size_t)BB * 32768];        // Wt frag images per batch
__device__ u32   g_Wt_lo[(size_t)BB * 32768];

// ---------------- helpers -----------------------------------------------------
__device__ __forceinline__ u32 pack2bf(float x, float y) {
    __nv_bfloat162 h = __floats2bfloat162_rn(x, y);   // lo = x, hi = y
    return *reinterpret_cast<u32*>(&h);
}
__device__ __forceinline__ void split2(float x, float y, u32& hi, u32& lo) {
    hi = pack2bf(x, y);
    const float hx = __uint_as_float((hi & 0xffffu) << 16);
    const float hy = __uint_as_float(hi & 0xffff0000u);
    lo = pack2bf(x - hx, y - hy);
}
__device__ __forceinline__ void mma16816(float* d, const u32* a, u32 b0, u32 b1) {
    asm volatile(
        "mma.sync.aligned.m16n8k16.row.col.f32.bf16.bf16.f32 "
        "{%0,%1,%2,%3}, {%4,%5,%6,%7}, {%8,%9}, {%0,%1,%2,%3};"
        : "+f"(d[0]), "+f"(d[1]), "+f"(d[2]), "+f"(d[3])
        : "r"(a[0]), "r"(a[1]), "r"(a[2]), "r"(a[3]), "r"(b0), "r"(b1));
}

// 4-pass split-bf16 MMA (AhBh, AhBl, AlBh, AlBl).
// A images: u32 rows of 132 words (264 bf16, padded). B frag images in gmem.
template<int NT>
__device__ __forceinline__ void gemm_mma(const u32* __restrict__ sAh,
                                         const u32* __restrict__ sAl,
                                         const u32* __restrict__ Bh,
                                         const u32* __restrict__ Bl,
                                         float acc[2][NT][4],
                                         int rowbase, int ntgbase, int lane)
{
    const int g = lane >> 2, t = lane & 3;
#pragma unroll 1
    for (int pass = 0; pass < 4; ++pass) {
        const u32* A = (pass & 2) ? sAl : sAh;
        const uint2* B = reinterpret_cast<const uint2*>((pass & 1) ? Bl : Bh);
#pragma unroll 1
        for (int k16 = 0; k16 < 16; ++k16) {
            u32 a[2][4];
#pragma unroll
            for (int mt = 0; mt < 2; ++mt) {
                const int wi = (rowbase + mt * 16 + g) * 132 + k16 * 8 + t;
                a[mt][0] = A[wi];
                a[mt][1] = A[wi + 8 * 132];
                a[mt][2] = A[wi + 4];
                a[mt][3] = A[wi + 8 * 132 + 4];
            }
            uint2 b[NT];
#pragma unroll
            for (int nt = 0; nt < NT; ++nt)
                b[nt] = B[(k16 * 32 + ntgbase + nt) * 32 + lane];
#pragma unroll
            for (int mt = 0; mt < 2; ++mt)
#pragma unroll
                for (int nt = 0; nt < NT; ++nt)
                    mma16816(acc[mt][nt], a[mt], b[nt].x, b[nt].y);
        }
    }
}

// ---------------- K0: pack weight fragment images ----------------------------
__global__ void __launch_bounds__(256)
k0_pack(const float* __restrict__ Wx, const float* __restrict__ Ws,
        const float* __restrict__ bs, const float* __restrict__ bx,
        const float* __restrict__ Wfx)
{
    const int pid = blockIdx.x * 256 + threadIdx.x;   // 65536
    const int img = pid >> 15;
    const int p = pid & 32767;
    const int r = p & 1, lane = (p >> 1) & 31, nt = (p >> 6) & 31, k16 = p >> 11;
    const int t = lane & 3, g = lane >> 2;
    const int k = k16 * 16 + r * 8 + 2 * t;
    const int n = nt * 8 + g;
    float v0, v1;
    if (img == 0) {
        const int h = n >> 5, gg = n & 31;
        float s0 = 0.f, s1 = 0.f;
#pragma unroll
        for (int d = 0; d < DD; ++d) {
            const float w = Ws[d * GG + gg];
            s0 = fmaf(Wx[k * 256 + h * 32 + d], w, s0);
            s1 = fmaf(Wx[(k + 1) * 256 + h * 32 + d], w, s1);
        }
        v0 = s0; v1 = s1;
    } else {
        v0 = Wfx[k * 256 + n];
        v1 = Wfx[(k + 1) * 256 + n];
    }
    u32 hi, lo;
    split2(v0, v1, hi, lo);
    if (img == 0) { g_Bxs_hi[p] = hi; g_Bxs_lo[p] = lo; }
    else          { g_Bfx_hi[p] = hi; g_Bfx_lo[p] = lo; }

    if (blockIdx.x == 0) {
        const int hg = threadIdx.x;
        const int h = hg >> 5, gg = hg & 31;
        float s = bs[gg];
#pragma unroll
        for (int d = 0; d < DD; ++d)
            s = fmaf(bx[h * 32 + d], Ws[d * GG + gg], s);
        g_blog[hg] = s;
    }
}

// ---------------- K1: LN + tensor GEMMs + softmax + partials ------------------
// smem: sA_hi u32[64][132] | sA_lo u32[64][132] | sF f32[64][264] | sInvt f32[8]
// after GEMM group 2, sA region is overlaid by sW f32[64][264] (exact size).
#define S1_ALO   33792
#define S1_F     67584
#define S1_INVT  (S1_F + 64 * 264 * 4)        // 135168
#define S1_TOTAL (S1_INVT + 64)

__global__ void __launch_bounds__(256, 1)
k1_dispatch(const float* __restrict__ fx,
            const float* __restrict__ ln_g, const float* __restrict__ ln_b,
            const float* __restrict__ bfx,  const float* __restrict__ tempp)
{
    extern __shared__ char smem[];
    u32*   sAh   = reinterpret_cast<u32*>(smem);
    u32*   sAl   = reinterpret_cast<u32*>(smem + S1_ALO);
    float* sW    = reinterpret_cast<float*>(smem);           // overlay after GEMM2
    float* sF    = reinterpret_cast<float*>(smem + S1_F);
    float* sInvt = reinterpret_cast<float*>(smem + S1_INVT);

    const int tid  = threadIdx.x;
    const int w    = tid >> 5;
    const int lane = tid & 31;
    const int g    = lane >> 2, t = lane & 3;
    const int mr   = w >> 2;
    const int nc   = w & 3;
    const int batch = blockIdx.x / BLKS1;
    const int n0    = (blockIdx.x % BLKS1) * TOK1;

    if (tid < HH) sInvt[tid] = 1.0f / tempp[tid];

    const float* fxp = fx + ((size_t)batch * NN + n0) * CC;
    for (int idx = tid * 4; idx < TOK1 * CC; idx += 1024) {
        const int row = idx >> 8, col = idx & 255;
        *reinterpret_cast<float4*>(&sF[row * 264 + col]) =
            *reinterpret_cast<const float4*>(&fxp[idx]);
    }
    __syncthreads();

    for (int rrow = w * 8; rrow < w * 8 + 8; ++rrow) {
        float s = 0.f, s2 = 0.f;
#pragma unroll
        for (int c = lane; c < CC; c += 32) {
            const float v = sF[rrow * 264 + c];
            s += v; s2 += v * v;
        }
#pragma unroll
        for (int o = 16; o; o >>= 1) {
            s  += __shfl_xor_sync(0xffffffffu, s,  o);
            s2 += __shfl_xor_sync(0xffffffffu, s2, o);
        }
        const float mu = s * (1.f / CC);
        const float rstd = rsqrtf(s2 * (1.f / CC) - mu * mu + 1e-5f);
#pragma unroll
        for (int c = lane; c < CC; c += 32) {
            const float v = sF[rrow * 264 + c];
            sF[rrow * 264 + c] = (v - mu) * rstd * ln_g[c] + ln_b[c];
        }
    }
    __syncthreads();

    for (int idx = tid; idx < 8192; idx += 256) {
        const int row = idx >> 7, cp = idx & 127;
        const float2 v = *reinterpret_cast<const float2*>(&sF[row * 264 + cp * 2]);
        u32 hi, lo;
        split2(v.x, v.y, hi, lo);
        sAh[row * 132 + cp] = hi;
        sAl[row * 132 + cp] = lo;
    }
    __syncthreads();

    // GEMM group 1: fx_mid -> sF
    {
        float acc[2][8][4];
#pragma unroll
        for (int mt = 0; mt < 2; ++mt)
#pragma unroll
            for (int nt = 0; nt < 8; ++nt)
#pragma unroll
                for (int i = 0; i < 4; ++i) acc[mt][nt][i] = 0.f;
        gemm_mma<8>(sAh, sAl, g_Bfx_hi, g_Bfx_lo, acc, mr * 32, nc * 8, lane);
#pragma unroll
        for (int mt = 0; mt < 2; ++mt)
#pragma unroll
            for (int nt = 0; nt < 8; ++nt) {
                const int r0 = mr * 32 + mt * 16 + g;
                const int c = nc * 64 + nt * 8 + 2 * t;
                const float b0 = bfx[c], b1 = bfx[c + 1];
                *reinterpret_cast<float2*>(&sF[r0 * 264 + c]) =
                    make_float2(acc[mt][nt][0] + b0, acc[mt][nt][1] + b1);
                *reinterpret_cast<float2*>(&sF[(r0 + 8) * 264 + c]) =
                    make_float2(acc[mt][nt][2] + b0, acc[mt][nt][3] + b1);
            }
    }
    __syncthreads();

    // GEMM group 2: logits -> softmax -> w
    float acc[2][8][4];
#pragma unroll
    for (int mt = 0; mt < 2; ++mt)
#pragma unroll
        for (int nt = 0; nt < 8; ++nt)
#pragma unroll
            for (int i = 0; i < 4; ++i) acc[mt][nt][i] = 0.f;
    gemm_mma<8>(sAh, sAl, g_Bxs_hi, g_Bxs_lo, acc, mr * 32, nc * 8, lane);
    __syncthreads();   // all warps done reading sAh/sAl -> region reusable as sW

#pragma unroll
    for (int mt = 0; mt < 2; ++mt)
#pragma unroll
        for (int nt = 0; nt < 8; ++nt) {
            const int c = nc * 64 + nt * 8 + 2 * t;
            const float iv = sInvt[c >> 5];
            const float b0 = g_blog[c], b1 = g_blog[c + 1];
            acc[mt][nt][0] = (acc[mt][nt][0] + b0) * iv;
            acc[mt][nt][1] = (acc[mt][nt][1] + b1) * iv;
            acc[mt][nt][2] = (acc[mt][nt][2] + b0) * iv;
            acc[mt][nt][3] = (acc[mt][nt][3] + b1) * iv;
        }

    // softmax over each head's 32 cols (4 n-tiles), per row variant
#pragma unroll
    for (int mt = 0; mt < 2; ++mt)
#pragma unroll
        for (int rv = 0; rv < 2; ++rv)
#pragma unroll
            for (int hh = 0; hh < 2; ++hh) {
                float mx = -1e30f;
#pragma unroll
                for (int j = 0; j < 4; ++j) {
                    mx = fmaxf(mx, acc[mt][hh * 4 + j][rv * 2]);
                    mx = fmaxf(mx, acc[mt][hh * 4 + j][rv * 2 + 1]);
                }
                mx = fmaxf(mx, __shfl_xor_sync(0xffffffffu, mx, 1));
                mx = fmaxf(mx, __shfl_xor_sync(0xffffffffu, mx, 2));
                float sum = 0.f;
#pragma unroll
                for (int j = 0; j < 4; ++j) {
                    float e0 = __expf(acc[mt][hh * 4 + j][rv * 2] - mx);
                    float e1 = __expf(acc[mt][hh * 4 + j][rv * 2 + 1] - mx);
                    acc[mt][hh * 4 + j][rv * 2] = e0;
                    acc[mt][hh * 4 + j][rv * 2 + 1] = e1;
                    sum += e0 + e1;
                }
                sum += __shfl_xor_sync(0xffffffffu, sum, 1);
                sum += __shfl_xor_sync(0xffffffffu, sum, 2);
                const float inv = 1.0f / sum;
#pragma unroll
                for (int j = 0; j < 4; ++j) {
                    acc[mt][hh * 4 + j][rv * 2] *= inv;
                    acc[mt][hh * 4 + j][rv * 2 + 1] *= inv;
                }
            }

    // write w: fp32 to smem sW + bf16 hi/lo to gmem
    {
        u32* gwh = reinterpret_cast<u32*>(g_w_hi);
        u32* gwl = reinterpret_cast<u32*>(g_w_lo);
#pragma unroll
        for (int mt = 0; mt < 2; ++mt)
#pragma unroll
            for (int nt = 0; nt < 8; ++nt) {
                const int r0 = mr * 32 + mt * 16 + g;
                const int c = nc * 64 + nt * 8 + 2 * t;
                *reinterpret_cast<float2*>(&sW[r0 * 264 + c]) =
                    make_float2(acc[mt][nt][0], acc[mt][nt][1]);
                *reinterpret_cast<float2*>(&sW[(r0 + 8) * 264 + c]) =
                    make_float2(acc[mt][nt][2], acc[mt][nt][3]);
                u32 hi, lo;
                split2(acc[mt][nt][0], acc[mt][nt][1], hi, lo);
                size_t bi = (((size_t)batch * NN + n0 + r0) * 256 + c) >> 1;
                gwh[bi] = hi; gwl[bi] = lo;
                split2(acc[mt][nt][2], acc[mt][nt][3], hi, lo);
                bi = (((size_t)batch * NN + n0 + r0 + 8) * 256 + c) >> 1;
                gwh[bi] = hi; gwl[bi] = lo;
            }
    }
    __syncthreads();

    // CORRECT partial accumulation: warp = head h, lane = slice g.
    // accT[d] = sum over ALL 64 rows of w[row][h*32+g] * fx_mid[row][h*32+d]
    {
        const int h = w;
        const int gcol = lane;
        float4 accT[8];
#pragma unroll
        for (int j = 0; j < 8; ++j) accT[j] = make_float4(0.f, 0.f, 0.f, 0.f);
        float accN = 0.f;
#pragma unroll 4
        for (int row = 0; row < TOK1; ++row) {
            const float wv = sW[row * 264 + h * 32 + gcol];
            accN += wv;
#pragma unroll
            for (int j = 0; j < 8; ++j) {
                const float4 f = *reinterpret_cast<const float4*>(
                    &sF[row * 264 + h * 32 + j * 4]);
                accT[j].x = fmaf(wv, f.x, accT[j].x);
                accT[j].y = fmaf(wv, f.y, accT[j].y);
                accT[j].z = fmaf(wv, f.z, accT[j].z);
                accT[j].w = fmaf(wv, f.w, accT[j].w);
            }
        }
        float4* pt = reinterpret_cast<float4*>(
            g_part_tok + ((size_t)blockIdx.x * 256 + h * 32 + gcol) * DD);
#pragma unroll
        for (int j = 0; j < 8; ++j) pt[j] = accT[j];
        g_part_norm[(size_t)blockIdx.x * 256 + h * 32 + gcol] = accN;
    }
}

// ---------------- K2: reduce + attention + MLP + Wt frag images ---------------
__global__ void __launch_bounds__(1024)
k2_tokens(const float* __restrict__ Wq, const float* __restrict__ Wk,
          const float* __restrict__ Wv,
          const float* __restrict__ tln_g, const float* __restrict__ tln_b,
          const float* __restrict__ W1, const float* __restrict__ b1,
          const float* __restrict__ W2, const float* __restrict__ b2,
          const float* __restrict__ Wo)
{
    const int b = blockIdx.x / HH;
    const int h = blockIdx.x % HH;
    const int tid = threadIdx.x;
    const int g = tid >> 5, d = tid & 31;

    __shared__ float s_st[GG][DD + 1];
    __shared__ float s_q[GG][DD + 1], s_k[GG][DD + 1], s_v[GG][DD + 1];
    __shared__ float s_attn[GG][GG + 1];
    __shared__ float s_h1[GG][4 * DD];
    __shared__ float s_norm[GG];
    __shared__ float s_tok2[GG][DD + 1];

    float tsum = 0.f;
#pragma unroll 4
    for (int pb = 0; pb < BLKS1; ++pb) {
        const size_t blk = (size_t)b * BLKS1 + pb;
        tsum += g_part_tok[(blk * 256 + h * GG + g) * DD + d];
    }
    if (tid < GG) {
        float ns = 0.f;
#pragma unroll 4
        for (int pb = 0; pb < BLKS1; ++pb) {
            const size_t blk = (size_t)b * BLKS1 + pb;
            ns += g_part_norm[blk * 256 + h * GG + tid];
        }
        s_norm[tid] = ns;
    }
    __syncthreads();

    const float st = tsum / (s_norm[g] + 1e-5f);
    s_st[g][d] = st;
    __syncthreads();

    float q = 0.f, kk = 0.f, vv = 0.f;
#pragma unroll
    for (int dd2 = 0; dd2 < DD; ++dd2) {
        const float sv = s_st[g][dd2];
        q  = fmaf(sv, Wq[dd2 * DD + d], q);
        kk = fmaf(sv, Wk[dd2 * DD + d], kk);
        vv = fmaf(sv, Wv[dd2 * DD + d], vv);
    }
    s_q[g][d] = q; s_k[g][d] = kk; s_v[g][d] = vv;
    __syncthreads();

    {
        const int kidx = d;
        float lg = 0.f;
#pragma unroll
        for (int dd2 = 0; dd2 < DD; ++dd2)
            lg = fmaf(s_q[g][dd2], s_k[kidx][dd2], lg);
        lg *= 0.17677669529663687f;
        float m = lg;
#pragma unroll
        for (int o = 16; o; o >>= 1) m = fmaxf(m, __shfl_xor_sync(0xffffffffu, m, o));
        const float e = __expf(lg - m);
        float ssum = e;
#pragma unroll
        for (int o = 16; o; o >>= 1) ssum += __shfl_xor_sync(0xffffffffu, ssum, o);
        s_attn[g][kidx] = e / ssum;
    }
    __syncthreads();

    float ot = st;
#pragma unroll
    for (int kidx = 0; kidx < GG; ++kidx)
        ot = fmaf(s_attn[g][kidx], s_v[kidx][d], ot);

    float s1 = ot, s2o = ot * ot;
#pragma unroll
    for (int o = 16; o; o >>= 1) {
        s1  += __shfl_xor_sync(0xffffffffu, s1,  o);
        s2o += __shfl_xor_sync(0xffffffffu, s2o, o);
    }
    const float mu = s1 * (1.f / DD);
    const float rstd = rsqrtf(s2o * (1.f / DD) - mu * mu + 1e-5f);
    const float hn = (ot - mu) * rstd * tln_g[d] + tln_b[d];
    __syncthreads();
    s_st[g][d] = hn;
    __syncthreads();

#pragma unroll
    for (int jj = 0; jj < 4; ++jj) {
        const int j = d + 32 * jj;
        float a = b1[j];
#pragma unroll
        for (int dd2 = 0; dd2 < DD; ++dd2)
            a = fmaf(s_st[g][dd2], W1[dd2 * (4 * DD) + j], a);
        a = 0.5f * a * (1.0f + erff(a * 0.70710678118654752f));
        s_h1[g][j] = a;
    }
    __syncthreads();

    float tk = b2[d];
#pragma unroll
    for (int j = 0; j < 4 * DD; ++j)
        tk = fmaf(s_h1[g][j], W2[j * DD + d], tk);
    tk += ot;
    s_tok2[g][d] = tk;
    __syncthreads();

    for (int idx = tid; idx < 4096; idx += 1024) {
        const int r = idx & 1;
        const int lane2 = (idx >> 1) & 31;
        const int nt = (idx >> 6) & 31;
        const int k16i = idx >> 11;
        const int t2 = lane2 & 3, g2 = lane2 >> 2;
        const int gl0 = k16i * 16 + r * 8 + 2 * t2;
        const int n = nt * 8 + g2;
        float v0 = 0.f, v1 = 0.f;
#pragma unroll
        for (int dd2 = 0; dd2 < DD; ++dd2) {
            const float wov = Wo[(h * DD + dd2) * CC + n];
            v0 = fmaf(s_tok2[gl0][dd2], wov, v0);
            v1 = fmaf(s_tok2[gl0 + 1][dd2], wov, v1);
        }
        u32 hi, lo;
        split2(v0, v1, hi, lo);
        const size_t oi = (size_t)b * 32768 +
            ((((size_t)(h * 2 + k16i) * 32 + nt) * 32 + lane2) * 2 + r);
        g_Wt_hi[oi] = hi;
        g_Wt_lo[oi] = lo;
    }
}

// ---------------- K3: out = w @ Wt + bo + LN(fx) -------------------------------
#define S3_ALO   67584
#define S3_MU    135168
#define S3_RS    (S3_MU + 512)
#define S3_TOTAL (S3_RS + 512)

__global__ void __launch_bounds__(512, 1)
k3_tc(const float* __restrict__ fx,
      const float* __restrict__ ln_g, const float* __restrict__ ln_b,
      const float* __restrict__ bo,  float* __restrict__ out)
{
    extern __shared__ char smem[];
    u32*   sAh = reinterpret_cast<u32*>(smem);
    u32*   sAl = reinterpret_cast<u32*>(smem + S3_ALO);
    float* sMu = reinterpret_cast<float*>(smem + S3_MU);
    float* sRs = reinterpret_cast<float*>(smem + S3_RS);

    const int tid  = threadIdx.x;
    const int w    = tid >> 5;
    const int lane = tid & 31;
    const int g    = lane >> 2, t = lane & 3;
    const int wr   = w >> 2;
    const int wn   = w & 3;
    const int batch = blockIdx.x / BLKS3;
    const int n0    = (blockIdx.x % BLKS3) * TOK3;

    {
        const u32* gwh = reinterpret_cast<const u32*>(g_w_hi) +
                         (((size_t)batch * NN + n0) * 256 >> 1);
        const u32* gwl = reinterpret_cast<const u32*>(g_w_lo) +
                         (((size_t)batch * NN + n0) * 256 >> 1);
        for (int idx = tid; idx < 128 * 128; idx += 512) {
            const int row = idx >> 7, cp = idx & 127;
            sAh[row * 132 + cp] = gwh[row * 128 + cp];
            sAl[row * 132 + cp] = gwl[row * 128 + cp];
        }
    }

    for (int i = 0; i < 8; ++i) {
        const int row = w * 8 + i;
        const float* rp = fx + ((size_t)batch * NN + n0 + row) * CC + lane * 8;
        const float4 f1 = *reinterpret_cast<const float4*>(rp);
        const float4 f2 = *reinterpret_cast<const float4*>(rp + 4);
        float s = f1.x + f1.y + f1.z + f1.w + f2.x + f2.y + f2.z + f2.w;
        float s2 = f1.x * f1.x + f1.y * f1.y + f1.z * f1.z + f1.w * f1.w +
                   f2.x * f2.x + f2.y * f2.y + f2.z * f2.z + f2.w * f2.w;
#pragma unroll
        for (int o = 16; o; o >>= 1) {
            s  += __shfl_xor_sync(0xffffffffu, s,  o);
            s2 += __shfl_xor_sync(0xffffffffu, s2, o);
        }
        if (lane == 0) {
            const float mu = s * (1.f / CC);
            sMu[row] = mu;
            sRs[row] = rsqrtf(s2 * (1.f / CC) - mu * mu + 1e-5f);
        }
    }
    __syncthreads();

    const u32* Bh = g_Wt_hi + (size_t)batch * 32768;
    const u32* Bl = g_Wt_lo + (size_t)batch * 32768;

#pragma unroll 1
    for (int ch = 0; ch < 2; ++ch) {
        float acc[2][4][4];
#pragma unroll
        for (int mt = 0; mt < 2; ++mt)
#pragma unroll
            for (int nt = 0; nt < 4; ++nt)
#pragma unroll
                for (int i = 0; i < 4; ++i) acc[mt][nt][i] = 0.f;

        gemm_mma<4>(sAh, sAl, Bh, Bl, acc, wr * 32, ch * 16 + wn * 4, lane);

#pragma unroll
        for (int mt = 0; mt < 2; ++mt)
#pragma unroll
            for (int nt = 0; nt < 4; ++nt) {
                const int c = ch * 128 + wn * 32 + nt * 8 + 2 * t;
                const float bo0 = bo[c], bo1 = bo[c + 1];
                const float lg0 = ln_g[c], lg1 = ln_g[c + 1];
                const float lb0 = ln_b[c], lb1 = ln_b[c + 1];
#pragma unroll
                for (int rv = 0; rv < 2; ++rv) {
                    const int row = wr * 32 + mt * 16 + g + rv * 8;
                    const size_t go = ((size_t)batch * NN + n0 + row) * 256 + c;
                    const float2 fv = *reinterpret_cast<const float2*>(&fx[go]);
                    const float mu = sMu[row], rs = sRs[row];
                    float2 o;
                    o.x = acc[mt][nt][rv * 2]     + bo0 + (fv.x - mu) * rs * lg0 + lb0;
                    o.y = acc[mt][nt][rv * 2 + 1] + bo1 + (fv.y - mu) * rs * lg1 + lb1;
                    *reinterpret_cast<float2*>(&out[go]) = o;
                }
            }
    }
}

// ---------------- launch -------------------------------------------------------
extern "C" void kernel_launch(void* const* d_in, const int* in_sizes, int n_in,
                              void* d_out, int out_size)
{
    const float* fx    = (const float*)d_in[0];
    const float* ln_g  = (const float*)d_in[1];
    const float* ln_b  = (const float*)d_in[2];
    const float* Wx    = (const float*)d_in[3];
    const float* bx    = (const float*)d_in[4];
    const float* Wfx   = (const float*)d_in[5];
    const float* bfx   = (const float*)d_in[6];
    const float* Ws    = (const float*)d_in[7];
    const float* bs    = (const float*)d_in[8];
    const float* tempp = (const float*)d_in[9];
    const float* Wq    = (const float*)d_in[10];
    const float* Wk    = (const float*)d_in[11];
    const float* Wv    = (const float*)d_in[12];
    const float* tln_g = (const float*)d_in[13];
    const float* tln_b = (const float*)d_in[14];
    const float* W1    = (const float*)d_in[15];
    const float* b1    = (const float*)d_in[16];
    const float* W2    = (const float*)d_in[17];
    const float* b2    = (const float*)d_in[18];
    const float* Wo    = (const float*)d_in[19];
    const float* bo    = (const float*)d_in[20];
    float* out = (float*)d_out;

    static int s_init = 0;
    if (!s_init) {
        cudaFuncSetAttribute(k1_dispatch, cudaFuncAttributeMaxDynamicSharedMemorySize, S1_TOTAL);
        cudaFuncSetAttribute(k3_tc, cudaFuncAttributeMaxDynamicSharedMemorySize, S3_TOTAL);
        s_init = 1;
    }

    k0_pack<<<256, 256>>>(Wx, Ws, bs, bx, Wfx);
    k1_dispatch<<<NBLK1, 256, S1_TOTAL>>>(fx, ln_g, ln_b, bfx, tempp);
    k2_tokens<<<BB * HH, 1024>>>(Wq, Wk, Wv, tln_g, tln_b, W1, b1, W2, b2, Wo);
    k3_tc<<<NBLK3, 512, S3_TOTAL>>>(fx, ln_g, ln_b, bo, out);
}

// round 10
// speedup vs baseline: 2.3066x; 1.4949x over previous
#include <cuda_runtime.h>
#include <cuda_bf16.h>
#include <math.h>
#include <cstdint>

#define BB 4
#define NN 32768
#define CC 256
#define HH 8
#define DD 32
#define GG 32
#define TOK1 64
#define BLKS1 (NN / TOK1)            // 512
#define NBLK1 (BB * BLKS1)           // 2048
#define NPART (NBLK1 * 2)            // 4096 partial blocks (2 halves per CTA)
#define PPB   (NPART / BB)           // 1024 partials per batch
#define TOK3 128
#define BLKS3 (NN / TOK3)            // 256
#define NBLK3 (BB * BLKS3)           // 1024

typedef unsigned int u32;
typedef unsigned short u16;

// ---------------- device scratch ---------------------------------------------
__device__ u32   g_Bxs_hi[32768], g_Bxs_lo[32768];   // WxWs frag images
__device__ u32   g_Bfx_hi[32768], g_Bfx_lo[32768];   // Wfx frag images
__device__ float g_blog[256];
__device__ u16   g_w_hi[(size_t)BB * NN * 256];      // slice_w bf16 hi [b][n][hg]
__device__ u16   g_w_lo[(size_t)BB * NN * 256];
__device__ float g_part_tok[(size_t)NPART * 256 * DD];
__device__ float g_part_norm[(size_t)NPART * 256];
__device__ float g_tok_red[(size_t)BB * 256 * DD];
__device__ float g_norm_red[(size_t)BB * 256];
__device__ u32   g_Wt_hi[(size_t)BB * 32768];        // Wt frag images per batch
__device__ u32   g_Wt_lo[(size_t)BB * 32768];

// ---------------- helpers -----------------------------------------------------
__device__ __forceinline__ u32 pack2bf(float x, float y) {
    __nv_bfloat162 h = __floats2bfloat162_rn(x, y);
    return *reinterpret_cast<u32*>(&h);
}
__device__ __forceinline__ void split2(float x, float y, u32& hi, u32& lo) {
    hi = pack2bf(x, y);
    const float hx = __uint_as_float((hi & 0xffffu) << 16);
    const float hy = __uint_as_float(hi & 0xffff0000u);
    lo = pack2bf(x - hx, y - hy);
}
__device__ __forceinline__ void mma16816(float* d, const u32* a, u32 b0, u32 b1) {
    asm volatile(
        "mma.sync.aligned.m16n8k16.row.col.f32.bf16.bf16.f32 "
        "{%0,%1,%2,%3}, {%4,%5,%6,%7}, {%8,%9}, {%0,%1,%2,%3};"
        : "+f"(d[0]), "+f"(d[1]), "+f"(d[2]), "+f"(d[3])
        : "r"(a[0]), "r"(a[1]), "r"(a[2]), "r"(a[3]), "r"(b0), "r"(b1));
}

// 3-pass split-bf16 MMA (AhBh, AhBl, AlBh), B frags from gmem with
// next-k16 register prefetch. A: u32 rows of 132 words in smem.
template<int NT>
__device__ __forceinline__ void gemm3(const u32* __restrict__ sAh,
                                      const u32* __restrict__ sAl,
                                      const u32* __restrict__ Bh,
                                      const u32* __restrict__ Bl,
                                      float acc[2][NT][4],
                                      int rowbase, int ntgbase, int lane)
{
    const int g = lane >> 2, t = lane & 3;
#pragma unroll 1
    for (int pass = 0; pass < 3; ++pass) {
        const u32* A = (pass == 2) ? sAl : sAh;
        const uint2* B = reinterpret_cast<const uint2*>((pass == 1) ? Bl : Bh);
        uint2 bb[NT];
#pragma unroll
        for (int nt = 0; nt < NT; ++nt)
            bb[nt] = B[(ntgbase + nt) * 32 + lane];
#pragma unroll 1
        for (int k16 = 0; k16 < 16; ++k16) {
            u32 a[2][4];
#pragma unroll
            for (int mt = 0; mt < 2; ++mt) {
                const int wi = (rowbase + mt * 16 + g) * 132 + k16 * 8 + t;
                a[mt][0] = A[wi];
                a[mt][1] = A[wi + 8 * 132];
                a[mt][2] = A[wi + 4];
                a[mt][3] = A[wi + 8 * 132 + 4];
            }
            uint2 bn[NT];
            if (k16 < 15) {
#pragma unroll
                for (int nt = 0; nt < NT; ++nt)
                    bn[nt] = B[((k16 + 1) * 32 + ntgbase + nt) * 32 + lane];
            }
#pragma unroll
            for (int mt = 0; mt < 2; ++mt)
#pragma unroll
                for (int nt = 0; nt < NT; ++nt)
                    mma16816(acc[mt][nt], a[mt], bb[nt].x, bb[nt].y);
#pragma unroll
            for (int nt = 0; nt < NT; ++nt) bb[nt] = bn[nt];
        }
    }
}

// ---------------- K0: pack weight fragment images ----------------------------
__global__ void __launch_bounds__(256)
k0_pack(const float* __restrict__ Wx, const float* __restrict__ Ws,
        const float* __restrict__ bs, const float* __restrict__ bx,
        const float* __restrict__ Wfx)
{
    const int pid = blockIdx.x * 256 + threadIdx.x;   // 65536
    const int img = pid >> 15;
    const int p = pid & 32767;
    const int r = p & 1, lane = (p >> 1) & 31, nt = (p >> 6) & 31, k16 = p >> 11;
    const int t = lane & 3, g = lane >> 2;
    const int k = k16 * 16 + r * 8 + 2 * t;
    const int n = nt * 8 + g;
    float v0, v1;
    if (img == 0) {
        const int h = n >> 5, gg = n & 31;
        float s0 = 0.f, s1 = 0.f;
#pragma unroll
        for (int d = 0; d < DD; ++d) {
            const float w = Ws[d * GG + gg];
            s0 = fmaf(Wx[k * 256 + h * 32 + d], w, s0);
            s1 = fmaf(Wx[(k + 1) * 256 + h * 32 + d], w, s1);
        }
        v0 = s0; v1 = s1;
    } else {
        v0 = Wfx[k * 256 + n];
        v1 = Wfx[(k + 1) * 256 + n];
    }
    u32 hi, lo;
    split2(v0, v1, hi, lo);
    if (img == 0) { g_Bxs_hi[p] = hi; g_Bxs_lo[p] = lo; }
    else          { g_Bfx_hi[p] = hi; g_Bfx_lo[p] = lo; }

    if (blockIdx.x == 0) {
        const int hg = threadIdx.x;
        const int h = hg >> 5, gg = hg & 31;
        float s = bs[gg];
#pragma unroll
        for (int d = 0; d < DD; ++d)
            s = fmaf(bx[h * 32 + d], Ws[d * GG + gg], s);
        g_blog[hg] = s;
    }
}

// ---------------- K1: LN + tensor GEMMs + softmax + partials (512 thr) --------
// smem: sA_hi u32[64][132] | sA_lo | sF f32[64][264] | sInvt f32[8]
// after GEMM2, sA region overlaid by sW f32[64][264].
#define S1_ALO   33792
#define S1_F     67584
#define S1_INVT  (S1_F + 64 * 264 * 4)        // 135168
#define S1_TOTAL (S1_INVT + 64)

__global__ void __launch_bounds__(512, 1)
k1_dispatch(const float* __restrict__ fx,
            const float* __restrict__ ln_g, const float* __restrict__ ln_b,
            const float* __restrict__ bfx,  const float* __restrict__ tempp)
{
    extern __shared__ char smem[];
    u32*   sAh   = reinterpret_cast<u32*>(smem);
    u32*   sAl   = reinterpret_cast<u32*>(smem + S1_ALO);
    float* sW    = reinterpret_cast<float*>(smem);           // overlay after GEMM2
    float* sF    = reinterpret_cast<float*>(smem + S1_F);
    float* sInvt = reinterpret_cast<float*>(smem + S1_INVT);

    const int tid  = threadIdx.x;
    const int w    = tid >> 5;            // 0..15
    const int lane = tid & 31;
    const int g    = lane >> 2, t = lane & 3;
    const int mr   = w >> 3;              // 0..1 row group of 32
    const int nc   = w & 7;               // 0..7 col group of 32 (= head)
    const int batch = blockIdx.x / BLKS1;
    const int n0    = (blockIdx.x % BLKS1) * TOK1;

    if (tid < HH) sInvt[tid] = 1.0f / tempp[tid];

    const float* fxp = fx + ((size_t)batch * NN + n0) * CC;
    for (int idx = tid * 4; idx < TOK1 * CC; idx += 2048) {
        const int row = idx >> 8, col = idx & 255;
        *reinterpret_cast<float4*>(&sF[row * 264 + col]) =
            *reinterpret_cast<const float4*>(&fxp[idx]);
    }
    __syncthreads();

    // LN: warp w handles rows w*4..+4
    for (int rrow = w * 4; rrow < w * 4 + 4; ++rrow) {
        float s = 0.f, s2 = 0.f;
#pragma unroll
        for (int c = lane; c < CC; c += 32) {
            const float v = sF[rrow * 264 + c];
            s += v; s2 += v * v;
        }
#pragma unroll
        for (int o = 16; o; o >>= 1) {
            s  += __shfl_xor_sync(0xffffffffu, s,  o);
            s2 += __shfl_xor_sync(0xffffffffu, s2, o);
        }
        const float mu = s * (1.f / CC);
        const float rstd = rsqrtf(s2 * (1.f / CC) - mu * mu + 1e-5f);
#pragma unroll
        for (int c = lane; c < CC; c += 32) {
            const float v = sF[rrow * 264 + c];
            sF[rrow * 264 + c] = (v - mu) * rstd * ln_g[c] + ln_b[c];
        }
    }
    __syncthreads();

    for (int idx = tid; idx < 8192; idx += 512) {
        const int row = idx >> 7, cp = idx & 127;
        const float2 v = *reinterpret_cast<const float2*>(&sF[row * 264 + cp * 2]);
        u32 hi, lo;
        split2(v.x, v.y, hi, lo);
        sAh[row * 132 + cp] = hi;
        sAl[row * 132 + cp] = lo;
    }
    __syncthreads();

    // GEMM group 1: fx_mid -> sF
    {
        float acc[2][4][4];
#pragma unroll
        for (int mt = 0; mt < 2; ++mt)
#pragma unroll
            for (int nt = 0; nt < 4; ++nt)
#pragma unroll
                for (int i = 0; i < 4; ++i) acc[mt][nt][i] = 0.f;
        gemm3<4>(sAh, sAl, g_Bfx_hi, g_Bfx_lo, acc, mr * 32, nc * 4, lane);
#pragma unroll
        for (int mt = 0; mt < 2; ++mt)
#pragma unroll
            for (int nt = 0; nt < 4; ++nt) {
                const int r0 = mr * 32 + mt * 16 + g;
                const int c = nc * 32 + nt * 8 + 2 * t;
                const float b0 = bfx[c], b1 = bfx[c + 1];
                *reinterpret_cast<float2*>(&sF[r0 * 264 + c]) =
                    make_float2(acc[mt][nt][0] + b0, acc[mt][nt][1] + b1);
                *reinterpret_cast<float2*>(&sF[(r0 + 8) * 264 + c]) =
                    make_float2(acc[mt][nt][2] + b0, acc[mt][nt][3] + b1);
            }
    }

    // GEMM group 2: logits -> softmax -> w
    float acc[2][4][4];
#pragma unroll
    for (int mt = 0; mt < 2; ++mt)
#pragma unroll
        for (int nt = 0; nt < 4; ++nt)
#pragma unroll
            for (int i = 0; i < 4; ++i) acc[mt][nt][i] = 0.f;
    gemm3<4>(sAh, sAl, g_Bxs_hi, g_Bxs_lo, acc, mr * 32, nc * 4, lane);
    __syncthreads();   // all warps done with sAh/sAl -> reusable as sW

    // bias + temperature (head = nc)
    {
        const float iv = sInvt[nc];
#pragma unroll
        for (int mt = 0; mt < 2; ++mt)
#pragma unroll
            for (int nt = 0; nt < 4; ++nt) {
                const int c = nc * 32 + nt * 8 + 2 * t;
                const float b0 = g_blog[c], b1 = g_blog[c + 1];
                acc[mt][nt][0] = (acc[mt][nt][0] + b0) * iv;
                acc[mt][nt][1] = (acc[mt][nt][1] + b1) * iv;
                acc[mt][nt][2] = (acc[mt][nt][2] + b0) * iv;
                acc[mt][nt][3] = (acc[mt][nt][3] + b1) * iv;
            }
    }

    // softmax over this head's 32 cols (4 nt x 8), per (mt, row variant)
#pragma unroll
    for (int mt = 0; mt < 2; ++mt)
#pragma unroll
        for (int rv = 0; rv < 2; ++rv) {
            float mx = -1e30f;
#pragma unroll
            for (int j = 0; j < 4; ++j) {
                mx = fmaxf(mx, acc[mt][j][rv * 2]);
                mx = fmaxf(mx, acc[mt][j][rv * 2 + 1]);
            }
            mx = fmaxf(mx, __shfl_xor_sync(0xffffffffu, mx, 1));
            mx = fmaxf(mx, __shfl_xor_sync(0xffffffffu, mx, 2));
            float sum = 0.f;
#pragma unroll
            for (int j = 0; j < 4; ++j) {
                float e0 = __expf(acc[mt][j][rv * 2] - mx);
                float e1 = __expf(acc[mt][j][rv * 2 + 1] - mx);
                acc[mt][j][rv * 2] = e0;
                acc[mt][j][rv * 2 + 1] = e1;
                sum += e0 + e1;
            }
            sum += __shfl_xor_sync(0xffffffffu, sum, 1);
            sum += __shfl_xor_sync(0xffffffffu, sum, 2);
            const float inv = 1.0f / sum;
#pragma unroll
            for (int j = 0; j < 4; ++j) {
                acc[mt][j][rv * 2] *= inv;
                acc[mt][j][rv * 2 + 1] *= inv;
            }
        }

    // write w: fp32 to smem sW + bf16 hi/lo to gmem
    {
        u32* gwh = reinterpret_cast<u32*>(g_w_hi);
        u32* gwl = reinterpret_cast<u32*>(g_w_lo);
#pragma unroll
        for (int mt = 0; mt < 2; ++mt)
#pragma unroll
            for (int nt = 0; nt < 4; ++nt) {
                const int r0 = mr * 32 + mt * 16 + g;
                const int c = nc * 32 + nt * 8 + 2 * t;
                *reinterpret_cast<float2*>(&sW[r0 * 264 + c]) =
                    make_float2(acc[mt][nt][0], acc[mt][nt][1]);
                *reinterpret_cast<float2*>(&sW[(r0 + 8) * 264 + c]) =
                    make_float2(acc[mt][nt][2], acc[mt][nt][3]);
                u32 hi, lo;
                split2(acc[mt][nt][0], acc[mt][nt][1], hi, lo);
                size_t bi = (((size_t)batch * NN + n0 + r0) * 256 + c) >> 1;
                gwh[bi] = hi; gwl[bi] = lo;
                split2(acc[mt][nt][2], acc[mt][nt][3], hi, lo);
                bi = (((size_t)batch * NN + n0 + r0 + 8) * 256 + c) >> 1;
                gwh[bi] = hi; gwl[bi] = lo;
            }
    }
    __syncthreads();

    // partial accumulation: warp = (half, head); lane = slice g.
    // accT[d] = sum over 32 rows (this half) of w[row][h*32+g]*fx_mid[row][h*32+d]
    {
        const int h = w & 7;
        const int half = w >> 3;
        const int rbase = half * 32;
        float4 accT[8];
#pragma unroll
        for (int j = 0; j < 8; ++j) accT[j] = make_float4(0.f, 0.f, 0.f, 0.f);
        float accN = 0.f;
#pragma unroll 4
        for (int rr = 0; rr < 32; ++rr) {
            const int row = rbase + rr;
            const float wv = sW[row * 264 + h * 32 + lane];
            accN += wv;
#pragma unroll
            for (int j = 0; j < 8; ++j) {
                const float4 f = *reinterpret_cast<const float4*>(
                    &sF[row * 264 + h * 32 + j * 4]);
                accT[j].x = fmaf(wv, f.x, accT[j].x);
                accT[j].y = fmaf(wv, f.y, accT[j].y);
                accT[j].z = fmaf(wv, f.z, accT[j].z);
                accT[j].w = fmaf(wv, f.w, accT[j].w);
            }
        }
        const size_t pb = (size_t)blockIdx.x * 2 + half;
        float4* pt = reinterpret_cast<float4*>(
            g_part_tok + (pb * 256 + h * 32 + lane) * DD);
#pragma unroll
        for (int j = 0; j < 8; ++j) pt[j] = accT[j];
        g_part_norm[pb * 256 + h * 32 + lane] = accN;
    }
}

// ---------------- K2a: parallel partial reduce ---------------------------------
__global__ void __launch_bounds__(256)
k2a_reduce()
{
    __shared__ float red[8][33];
    __shared__ float rn[256];
    const int b  = blockIdx.x >> 8;
    const int hg = blockIdx.x & 255;
    const int tid = threadIdx.x;
    const int d = tid & 31, ck = tid >> 5;

    const float* base = g_part_tok + ((size_t)(b * PPB) * 256 + hg) * DD + d;
    float s = 0.f;
#pragma unroll 8
    for (int i = 0; i < PPB / 8; ++i)
        s += base[(size_t)(ck * (PPB / 8) + i) * (256 * DD)];
    red[ck][d] = s;

    float ns = 0.f;
#pragma unroll
    for (int j = 0; j < PPB / 256; ++j)
        ns += g_part_norm[(size_t)(b * PPB + tid * (PPB / 256) + j) * 256 + hg];
    rn[tid] = ns;
    __syncthreads();

    if (tid < 32) {
        float tot = 0.f;
#pragma unroll
        for (int c = 0; c < 8; ++c) tot += red[c][tid];
        g_tok_red[((size_t)b * 256 + hg) * DD + tid] = tot;
        float nsum = 0.f;
#pragma unroll
        for (int c = 0; c < 8; ++c) nsum += rn[tid + c * 32];
#pragma unroll
        for (int o = 16; o; o >>= 1) nsum += __shfl_xor_sync(0xffffffffu, nsum, o);
        if (tid == 0) g_norm_red[(size_t)b * 256 + hg] = nsum;
    }
}

// ---------------- K2b: attention + MLP + Wt frag images ------------------------
__global__ void __launch_bounds__(1024)
k2_tokens(const float* __restrict__ Wq, const float* __restrict__ Wk,
          const float* __restrict__ Wv,
          const float* __restrict__ tln_g, const float* __restrict__ tln_b,
          const float* __restrict__ W1, const float* __restrict__ b1,
          const float* __restrict__ W2, const float* __restrict__ b2,
          const float* __restrict__ Wo)
{
    const int b = blockIdx.x / HH;
    const int h = blockIdx.x % HH;
    const int tid = threadIdx.x;
    const int g = tid >> 5, d = tid & 31;

    __shared__ float s_st[GG][DD + 1];
    __shared__ float s_q[GG][DD + 1], s_k[GG][DD + 1], s_v[GG][DD + 1];
    __shared__ float s_attn[GG][GG + 1];
    __shared__ float s_h1[GG][4 * DD];
    __shared__ float s_tok2[GG][DD + 1];

    const float st = g_tok_red[((size_t)b * 256 + h * GG + g) * DD + d] /
                     (g_norm_red[(size_t)b * 256 + h * GG + g] + 1e-5f);
    s_st[g][d] = st;
    __syncthreads();

    float q = 0.f, kk = 0.f, vv = 0.f;
#pragma unroll
    for (int dd2 = 0; dd2 < DD; ++dd2) {
        const float sv = s_st[g][dd2];
        q  = fmaf(sv, Wq[dd2 * DD + d], q);
        kk = fmaf(sv, Wk[dd2 * DD + d], kk);
        vv = fmaf(sv, Wv[dd2 * DD + d], vv);
    }
    s_q[g][d] = q; s_k[g][d] = kk; s_v[g][d] = vv;
    __syncthreads();

    {
        const int kidx = d;
        float lg = 0.f;
#pragma unroll
        for (int dd2 = 0; dd2 < DD; ++dd2)
            lg = fmaf(s_q[g][dd2], s_k[kidx][dd2], lg);
        lg *= 0.17677669529663687f;
        float m = lg;
#pragma unroll
        for (int o = 16; o; o >>= 1) m = fmaxf(m, __shfl_xor_sync(0xffffffffu, m, o));
        const float e = __expf(lg - m);
        float ssum = e;
#pragma unroll
        for (int o = 16; o; o >>= 1) ssum += __shfl_xor_sync(0xffffffffu, ssum, o);
        s_attn[g][kidx] = e / ssum;
    }
    __syncthreads();

    float ot = st;
#pragma unroll
    for (int kidx = 0; kidx < GG; ++kidx)
        ot = fmaf(s_attn[g][kidx], s_v[kidx][d], ot);

    float s1 = ot, s2o = ot * ot;
#pragma unroll
    for (int o = 16; o; o >>= 1) {
        s1  += __shfl_xor_sync(0xffffffffu, s1,  o);
        s2o += __shfl_xor_sync(0xffffffffu, s2o, o);
    }
    const float mu = s1 * (1.f / DD);
    const float rstd = rsqrtf(s2o * (1.f / DD) - mu * mu + 1e-5f);
    const float hn = (ot - mu) * rstd * tln_g[d] + tln_b[d];
    __syncthreads();
    s_st[g][d] = hn;
    __syncthreads();

#pragma unroll
    for (int jj = 0; jj < 4; ++jj) {
        const int j = d + 32 * jj;
        float a = b1[j];
#pragma unroll
        for (int dd2 = 0; dd2 < DD; ++dd2)
            a = fmaf(s_st[g][dd2], W1[dd2 * (4 * DD) + j], a);
        a = 0.5f * a * (1.0f + erff(a * 0.70710678118654752f));
        s_h1[g][j] = a;
    }
    __syncthreads();

    float tk = b2[d];
#pragma unroll
    for (int j = 0; j < 4 * DD; ++j)
        tk = fmaf(s_h1[g][j], W2[j * DD + d], tk);
    tk += ot;
    s_tok2[g][d] = tk;
    __syncthreads();

    for (int idx = tid; idx < 4096; idx += 1024) {
        const int r = idx & 1;
        const int lane2 = (idx >> 1) & 31;
        const int nt = (idx >> 6) & 31;
        const int k16i = idx >> 11;
        const int t2 = lane2 & 3, g2 = lane2 >> 2;
        const int gl0 = k16i * 16 + r * 8 + 2 * t2;
        const int n = nt * 8 + g2;
        float v0 = 0.f, v1 = 0.f;
#pragma unroll
        for (int dd2 = 0; dd2 < DD; ++dd2) {
            const float wov = Wo[(h * DD + dd2) * CC + n];
            v0 = fmaf(s_tok2[gl0][dd2], wov, v0);
            v1 = fmaf(s_tok2[gl0 + 1][dd2], wov, v1);
        }
        u32 hi, lo;
        split2(v0, v1, hi, lo);
        const size_t oi = (size_t)b * 32768 +
            ((((size_t)(h * 2 + k16i) * 32 + nt) * 32 + lane2) * 2 + r);
        g_Wt_hi[oi] = hi;
        g_Wt_lo[oi] = lo;
    }
}

// ---------------- K3: out = w @ Wt + bo + LN(fx), smem-staged B ----------------
// smem: sA_hi u32[128][132] | sA_lo | sB uint2[8192] (64KB) | sMu[128] | sRs[128]
#define S3_ALO   67584
#define S3_B     135168
#define S3_MU    (S3_B + 65536)       // 200704
#define S3_RS    (S3_MU + 512)
#define S3_TOTAL (S3_RS + 512)

__global__ void __launch_bounds__(512, 1)
k3_tc(const float* __restrict__ fx,
      const float* __restrict__ ln_g, const float* __restrict__ ln_b,
      const float* __restrict__ bo,  float* __restrict__ out)
{
    extern __shared__ char smem[];
    u32*   sAh = reinterpret_cast<u32*>(smem);
    u32*   sAl = reinterpret_cast<u32*>(smem + S3_ALO);
    uint2* sB  = reinterpret_cast<uint2*>(smem + S3_B);
    float* sMu = reinterpret_cast<float*>(smem + S3_MU);
    float* sRs = reinterpret_cast<float*>(smem + S3_RS);

    const int tid  = threadIdx.x;
    const int w    = tid >> 5;
    const int lane = tid & 31;
    const int g    = lane >> 2, t = lane & 3;
    const int wr   = w >> 2;
    const int wn   = w & 3;
    const int batch = blockIdx.x / BLKS3;
    const int n0    = (blockIdx.x % BLKS3) * TOK3;

    {
        const u32* gwh = reinterpret_cast<const u32*>(g_w_hi) +
                         (((size_t)batch * NN + n0) * 256 >> 1);
        const u32* gwl = reinterpret_cast<const u32*>(g_w_lo) +
                         (((size_t)batch * NN + n0) * 256 >> 1);
        for (int idx = tid; idx < 128 * 128; idx += 512) {
            const int row = idx >> 7, cp = idx & 127;
            sAh[row * 132 + cp] = gwh[row * 128 + cp];
            sAl[row * 132 + cp] = gwl[row * 128 + cp];
        }
    }

    for (int i = 0; i < 8; ++i) {
        const int row = w * 8 + i;
        const float* rp = fx + ((size_t)batch * NN + n0 + row) * CC + lane * 8;
        const float4 f1 = *reinterpret_cast<const float4*>(rp);
        const float4 f2 = *reinterpret_cast<const float4*>(rp + 4);
        float s = f1.x + f1.y + f1.z + f1.w + f2.x + f2.y + f2.z + f2.w;
        float s2 = f1.x * f1.x + f1.y * f1.y + f1.z * f1.z + f1.w * f1.w +
                   f2.x * f2.x + f2.y * f2.y + f2.z * f2.z + f2.w * f2.w;
#pragma unroll
        for (int o = 16; o; o >>= 1) {
            s  += __shfl_xor_sync(0xffffffffu, s,  o);
            s2 += __shfl_xor_sync(0xffffffffu, s2, o);
        }
        if (lane == 0) {
            const float mu = s * (1.f / CC);
            sMu[row] = mu;
            sRs[row] = rsqrtf(s2 * (1.f / CC) - mu * mu + 1e-5f);
        }
    }

    const uint2* BhG = reinterpret_cast<const uint2*>(g_Wt_hi + (size_t)batch * 32768);
    const uint2* BlG = reinterpret_cast<const uint2*>(g_Wt_lo + (size_t)batch * 32768);

#pragma unroll 1
    for (int ch = 0; ch < 2; ++ch) {
        float acc[2][4][4];
#pragma unroll
        for (int mt = 0; mt < 2; ++mt)
#pragma unroll
            for (int nt = 0; nt < 4; ++nt)
#pragma unroll
                for (int i = 0; i < 4; ++i) acc[mt][nt][i] = 0.f;

#pragma unroll 1
        for (int pass = 0; pass < 3; ++pass) {
            const uint2* Bsrc = (pass == 1) ? BlG : BhG;
            const u32* A = (pass == 2) ? sAl : sAh;
            __syncthreads();
            // stage 64KB subimage: (k16, nt16 in ch window, lane)
#pragma unroll
            for (int i = 0; i < 16; ++i) {
                const int o = tid + i * 512;               // 0..8191
                const int k16s = o >> 9;
                sB[o] = Bsrc[o + k16s * 512 + ch * 512];   // src = k16*1024 + ch*512 + rem
            }
            __syncthreads();
#pragma unroll 1
            for (int k16 = 0; k16 < 16; ++k16) {
                u32 a[2][4];
#pragma unroll
                for (int mt = 0; mt < 2; ++mt) {
                    const int wi = (wr * 32 + mt * 16 + g) * 132 + k16 * 8 + t;
                    a[mt][0] = A[wi];
                    a[mt][1] = A[wi + 8 * 132];
                    a[mt][2] = A[wi + 4];
                    a[mt][3] = A[wi + 8 * 132 + 4];
                }
                uint2 b[4];
#pragma unroll
                for (int nt = 0; nt < 4; ++nt)
                    b[nt] = sB[k16 * 512 + (wn * 4 + nt) * 32 + lane];
#pragma unroll
                for (int mt = 0; mt < 2; ++mt)
#pragma unroll
                    for (int nt = 0; nt < 4; ++nt)
                        mma16816(acc[mt][nt], a[mt], b[nt].x, b[nt].y);
            }
        }

        // epilogue for this ch
#pragma unroll
        for (int mt = 0; mt < 2; ++mt)
#pragma unroll
            for (int nt = 0; nt < 4; ++nt) {
                const int c = ch * 128 + wn * 32 + nt * 8 + 2 * t;
                const float bo0 = bo[c], bo1 = bo[c + 1];
                const float lg0 = ln_g[c], lg1 = ln_g[c + 1];
                const float lb0 = ln_b[c], lb1 = ln_b[c + 1];
#pragma unroll
                for (int rv = 0; rv < 2; ++rv) {
                    const int row = wr * 32 + mt * 16 + g + rv * 8;
                    const size_t go = ((size_t)batch * NN + n0 + row) * 256 + c;
                    const float2 fv = *reinterpret_cast<const float2*>(&fx[go]);
                    const float mu = sMu[row], rs = sRs[row];
                    float2 o;
                    o.x = acc[mt][nt][rv * 2]     + bo0 + (fv.x - mu) * rs * lg0 + lb0;
                    o.y = acc[mt][nt][rv * 2 + 1] + bo1 + (fv.y - mu) * rs * lg1 + lb1;
                    *reinterpret_cast<float2*>(&out[go]) = o;
                }
            }
    }
}

// ---------------- launch -------------------------------------------------------
extern "C" void kernel_launch(void* const* d_in, const int* in_sizes, int n_in,
                              void* d_out, int out_size)
{
    const float* fx    = (const float*)d_in[0];
    const float* ln_g  = (const float*)d_in[1];
    const float* ln_b  = (const float*)d_in[2];
    const float* Wx    = (const float*)d_in[3];
    const float* bx    = (const float*)d_in[4];
    const float* Wfx   = (const float*)d_in[5];
    const float* bfx   = (const float*)d_in[6];
    const float* Ws    = (const float*)d_in[7];
    const float* bs    = (const float*)d_in[8];
    const float* tempp = (const float*)d_in[9];
    const float* Wq    = (const float*)d_in[10];
    const float* Wk    = (const float*)d_in[11];
    const float* Wv    = (const float*)d_in[12];
    const float* tln_g = (const float*)d_in[13];
    const float* tln_b = (const float*)d_in[14];
    const float* W1    = (const float*)d_in[15];
    const float* b1    = (const float*)d_in[16];
    const float* W2    = (const float*)d_in[17];
    const float* b2    = (const float*)d_in[18];
    const float* Wo    = (const float*)d_in[19];
    const float* bo    = (const float*)d_in[20];
    float* out = (float*)d_out;

    static int s_init = 0;
    if (!s_init) {
        cudaFuncSetAttribute(k1_dispatch, cudaFuncAttributeMaxDynamicSharedMemorySize, S1_TOTAL);
        cudaFuncSetAttribute(k3_tc, cudaFuncAttributeMaxDynamicSharedMemorySize, S3_TOTAL);
        s_init = 1;
    }

    k0_pack<<<256, 256>>>(Wx, Ws, bs, bx, Wfx);
    k1_dispatch<<<NBLK1, 512, S1_TOTAL>>>(fx, ln_g, ln_b, bfx, tempp);
    k2a_reduce<<<BB * 256, 256>>>();
    k2_tokens<<<BB * HH, 1024>>>(Wq, Wk, Wv, tln_g, tln_b, W1, b1, W2, b2, Wo);
    k3_tc<<<NBLK3, 512, S3_TOTAL>>>(fx, ln_g, ln_b, bo, out);
}

// round 11
// speedup vs baseline: 2.5365x; 1.0996x over previous
#include <cuda_runtime.h>
#include <cuda_bf16.h>
#include <math.h>
#include <cstdint>

#define BB 4
#define NN 32768
#define CC 256
#define HH 8
#define DD 32
#define GG 32
#define TOK1 64
#define BLKS1 (NN / TOK1)            // 512
#define NBLK1 (BB * BLKS1)           // 2048
#define NPART (NBLK1 * 2)            // 4096 partial blocks (2 halves per CTA)
#define PPB   (NPART / BB)           // 1024 partials per batch
#define TOK3 128
#define BLKS3 (NN / TOK3)            // 256
#define NBLK3 (BB * BLKS3)           // 1024

typedef unsigned int u32;
typedef unsigned short u16;

// ---------------- device scratch ---------------------------------------------
__device__ u32   g_Bxs_hi[32768], g_Bxs_lo[32768];   // WxWs frag images
__device__ u32   g_Bfx_hi[32768], g_Bfx_lo[32768];   // Wfx frag images
__device__ float g_blog[256];
__device__ u16   g_w_hi[(size_t)BB * NN * 256];      // slice_w bf16 hi [b][n][hg]
__device__ u16   g_w_lo[(size_t)BB * NN * 256];
__device__ float g_part_tok[(size_t)NPART * 256 * DD];
__device__ float g_part_norm[(size_t)NPART * 256];
__device__ float g_tok_red[(size_t)BB * 256 * DD];
__device__ float g_norm_red[(size_t)BB * 256];
__device__ u32   g_Wt_hi[(size_t)BB * 32768];        // Wt frag images per batch
__device__ u32   g_Wt_lo[(size_t)BB * 32768];

// ---------------- helpers -----------------------------------------------------
__device__ __forceinline__ u32 pack2bf(float x, float y) {
    __nv_bfloat162 h = __floats2bfloat162_rn(x, y);
    return *reinterpret_cast<u32*>(&h);
}
__device__ __forceinline__ void split2(float x, float y, u32& hi, u32& lo) {
    hi = pack2bf(x, y);
    const float hx = __uint_as_float((hi & 0xffffu) << 16);
    const float hy = __uint_as_float(hi & 0xffff0000u);
    lo = pack2bf(x - hx, y - hy);
}
__device__ __forceinline__ void mma16816(float* d, const u32* a, u32 b0, u32 b1) {
    asm volatile(
        "mma.sync.aligned.m16n8k16.row.col.f32.bf16.bf16.f32 "
        "{%0,%1,%2,%3}, {%4,%5,%6,%7}, {%8,%9}, {%0,%1,%2,%3};"
        : "+f"(d[0]), "+f"(d[1]), "+f"(d[2]), "+f"(d[3])
        : "r"(a[0]), "r"(a[1]), "r"(a[2]), "r"(a[3]), "r"(b0), "r"(b1));
}

// ---------------- K0: pack weight fragment images ----------------------------
__global__ void __launch_bounds__(256)
k0_pack(const float* __restrict__ Wx, const float* __restrict__ Ws,
        const float* __restrict__ bs, const float* __restrict__ bx,
        const float* __restrict__ Wfx)
{
    const int pid = blockIdx.x * 256 + threadIdx.x;   // 65536
    const int img = pid >> 15;
    const int p = pid & 32767;
    const int r = p & 1, lane = (p >> 1) & 31, nt = (p >> 6) & 31, k16 = p >> 11;
    const int t = lane & 3, g = lane >> 2;
    const int k = k16 * 16 + r * 8 + 2 * t;
    const int n = nt * 8 + g;
    float v0, v1;
    if (img == 0) {
        const int h = n >> 5, gg = n & 31;
        float s0 = 0.f, s1 = 0.f;
#pragma unroll
        for (int d = 0; d < DD; ++d) {
            const float w = Ws[d * GG + gg];
            s0 = fmaf(Wx[k * 256 + h * 32 + d], w, s0);
            s1 = fmaf(Wx[(k + 1) * 256 + h * 32 + d], w, s1);
        }
        v0 = s0; v1 = s1;
    } else {
        v0 = Wfx[k * 256 + n];
        v1 = Wfx[(k + 1) * 256 + n];
    }
    u32 hi, lo;
    split2(v0, v1, hi, lo);
    if (img == 0) { g_Bxs_hi[p] = hi; g_Bxs_lo[p] = lo; }
    else          { g_Bfx_hi[p] = hi; g_Bfx_lo[p] = lo; }

    if (blockIdx.x == 0) {
        const int hg = threadIdx.x;
        const int h = hg >> 5, gg = hg & 31;
        float s = bs[gg];
#pragma unroll
        for (int d = 0; d < DD; ++d)
            s = fmaf(bx[h * 32 + d], Ws[d * GG + gg], s);
        g_blog[hg] = s;
    }
}

// ---------------- K1: LN + merged tensor GEMM + softmax + partials ------------
// smem: sA_hi u32[64][132] | sA_lo | sF f32[64][264] | sInvt f32[8]
// after GEMM, sA region overlaid by sW f32[64][264].
// warp mapping for GEMM: gi = w>>3 (0: fx_mid, 1: logits), h = w&7.
// Each warp covers ALL 64 rows (4 mt groups) x 32 cols of its head -> no
// duplicated B-fragment reads (halves L2 traffic).
#define S1_ALO   33792
#define S1_F     67584
#define S1_INVT  (S1_F + 64 * 264 * 4)        // 135168
#define S1_TOTAL (S1_INVT + 64)

__global__ void __launch_bounds__(512, 1)
k1_dispatch(const float* __restrict__ fx,
            const float* __restrict__ ln_g, const float* __restrict__ ln_b,
            const float* __restrict__ bfx,  const float* __restrict__ tempp)
{
    extern __shared__ char smem[];
    u32*   sAh   = reinterpret_cast<u32*>(smem);
    u32*   sAl   = reinterpret_cast<u32*>(smem + S1_ALO);
    float* sW    = reinterpret_cast<float*>(smem);           // overlay after GEMM
    float* sF    = reinterpret_cast<float*>(smem + S1_F);
    float* sInvt = reinterpret_cast<float*>(smem + S1_INVT);

    const int tid  = threadIdx.x;
    const int w    = tid >> 5;            // 0..15
    const int lane = tid & 31;
    const int g    = lane >> 2, t = lane & 3;
    const int gi   = w >> 3;              // 0: fx_mid GEMM, 1: logits GEMM
    const int h    = w & 7;               // head
    const int batch = blockIdx.x / BLKS1;
    const int n0    = (blockIdx.x % BLKS1) * TOK1;

    if (tid < HH) sInvt[tid] = 1.0f / tempp[tid];

    const float* fxp = fx + ((size_t)batch * NN + n0) * CC;
    for (int idx = tid * 4; idx < TOK1 * CC; idx += 2048) {
        const int row = idx >> 8, col = idx & 255;
        *reinterpret_cast<float4*>(&sF[row * 264 + col]) =
            *reinterpret_cast<const float4*>(&fxp[idx]);
    }
    __syncthreads();

    // LN: warp w handles rows w*4..+4
    for (int rrow = w * 4; rrow < w * 4 + 4; ++rrow) {
        float s = 0.f, s2 = 0.f;
#pragma unroll
        for (int c = lane; c < CC; c += 32) {
            const float v = sF[rrow * 264 + c];
            s += v; s2 += v * v;
        }
#pragma unroll
        for (int o = 16; o; o >>= 1) {
            s  += __shfl_xor_sync(0xffffffffu, s,  o);
            s2 += __shfl_xor_sync(0xffffffffu, s2, o);
        }
        const float mu = s * (1.f / CC);
        const float rstd = rsqrtf(s2 * (1.f / CC) - mu * mu + 1e-5f);
#pragma unroll
        for (int c = lane; c < CC; c += 32) {
            const float v = sF[rrow * 264 + c];
            sF[rrow * 264 + c] = (v - mu) * rstd * ln_g[c] + ln_b[c];
        }
    }
    __syncthreads();

    for (int idx = tid; idx < 8192; idx += 512) {
        const int row = idx >> 7, cp = idx & 127;
        const float2 v = *reinterpret_cast<const float2*>(&sF[row * 264 + cp * 2]);
        u32 hi, lo;
        split2(v.x, v.y, hi, lo);
        sAh[row * 132 + cp] = hi;
        sAl[row * 132 + cp] = lo;
    }
    __syncthreads();

    // Merged GEMM: 64 rows x 32 cols per warp, 3 split passes, reg prefetch.
    float acc[4][4][4];
#pragma unroll
    for (int mt = 0; mt < 4; ++mt)
#pragma unroll
        for (int nt = 0; nt < 4; ++nt)
#pragma unroll
            for (int i = 0; i < 4; ++i) acc[mt][nt][i] = 0.f;

    const u32* BH = gi ? g_Bxs_hi : g_Bfx_hi;
    const u32* BL = gi ? g_Bxs_lo : g_Bfx_lo;
#pragma unroll 1
    for (int pass = 0; pass < 3; ++pass) {
        const u32* A = (pass == 2) ? sAl : sAh;
        const uint2* B = reinterpret_cast<const uint2*>((pass == 1) ? BL : BH);
        uint2 bb[4];
#pragma unroll
        for (int nt = 0; nt < 4; ++nt)
            bb[nt] = B[(h * 4 + nt) * 32 + lane];
#pragma unroll 1
        for (int k16 = 0; k16 < 16; ++k16) {
            u32 a[4][4];
#pragma unroll
            for (int mt = 0; mt < 4; ++mt) {
                const int wi = (mt * 16 + g) * 132 + k16 * 8 + t;
                a[mt][0] = A[wi];
                a[mt][1] = A[wi + 8 * 132];
                a[mt][2] = A[wi + 4];
                a[mt][3] = A[wi + 8 * 132 + 4];
            }
            uint2 bn[4];
            if (k16 < 15) {
#pragma unroll
                for (int nt = 0; nt < 4; ++nt)
                    bn[nt] = B[((k16 + 1) * 32 + h * 4 + nt) * 32 + lane];
            }
#pragma unroll
            for (int mt = 0; mt < 4; ++mt)
#pragma unroll
                for (int nt = 0; nt < 4; ++nt)
                    mma16816(acc[mt][nt], a[mt], bb[nt].x, bb[nt].y);
#pragma unroll
            for (int nt = 0; nt < 4; ++nt) bb[nt] = bn[nt];
        }
    }
    __syncthreads();   // all warps done with sAh/sAl -> region reusable as sW

    if (gi == 0) {
        // fx_mid epilogue -> sF
#pragma unroll
        for (int mt = 0; mt < 4; ++mt)
#pragma unroll
            for (int nt = 0; nt < 4; ++nt) {
                const int r0 = mt * 16 + g;
                const int c = h * 32 + nt * 8 + 2 * t;
                const float b0 = bfx[c], b1 = bfx[c + 1];
                *reinterpret_cast<float2*>(&sF[r0 * 264 + c]) =
                    make_float2(acc[mt][nt][0] + b0, acc[mt][nt][1] + b1);
                *reinterpret_cast<float2*>(&sF[(r0 + 8) * 264 + c]) =
                    make_float2(acc[mt][nt][2] + b0, acc[mt][nt][3] + b1);
            }
    } else {
        // logits: bias + temperature, softmax over this head's 32 cols
        const float iv = sInvt[h];
#pragma unroll
        for (int mt = 0; mt < 4; ++mt)
#pragma unroll
            for (int nt = 0; nt < 4; ++nt) {
                const int c = h * 32 + nt * 8 + 2 * t;
                const float b0 = g_blog[c], b1 = g_blog[c + 1];
                acc[mt][nt][0] = (acc[mt][nt][0] + b0) * iv;
                acc[mt][nt][1] = (acc[mt][nt][1] + b1) * iv;
                acc[mt][nt][2] = (acc[mt][nt][2] + b0) * iv;
                acc[mt][nt][3] = (acc[mt][nt][3] + b1) * iv;
            }
#pragma unroll
        for (int mt = 0; mt < 4; ++mt)
#pragma unroll
            for (int rv = 0; rv < 2; ++rv) {
                float mx = -1e30f;
#pragma unroll
                for (int j = 0; j < 4; ++j) {
                    mx = fmaxf(mx, acc[mt][j][rv * 2]);
                    mx = fmaxf(mx, acc[mt][j][rv * 2 + 1]);
                }
                mx = fmaxf(mx, __shfl_xor_sync(0xffffffffu, mx, 1));
                mx = fmaxf(mx, __shfl_xor_sync(0xffffffffu, mx, 2));
                float sum = 0.f;
#pragma unroll
                for (int j = 0; j < 4; ++j) {
                    float e0 = __expf(acc[mt][j][rv * 2] - mx);
                    float e1 = __expf(acc[mt][j][rv * 2 + 1] - mx);
                    acc[mt][j][rv * 2] = e0;
                    acc[mt][j][rv * 2 + 1] = e1;
                    sum += e0 + e1;
                }
                sum += __shfl_xor_sync(0xffffffffu, sum, 1);
                sum += __shfl_xor_sync(0xffffffffu, sum, 2);
                const float inv = 1.0f / sum;
#pragma unroll
                for (int j = 0; j < 4; ++j) {
                    acc[mt][j][rv * 2] *= inv;
                    acc[mt][j][rv * 2 + 1] *= inv;
                }
            }
        // write w: fp32 to sW + bf16 hi/lo to gmem
        u32* gwh = reinterpret_cast<u32*>(g_w_hi);
        u32* gwl = reinterpret_cast<u32*>(g_w_lo);
#pragma unroll
        for (int mt = 0; mt < 4; ++mt)
#pragma unroll
            for (int nt = 0; nt < 4; ++nt) {
                const int r0 = mt * 16 + g;
                const int c = h * 32 + nt * 8 + 2 * t;
                *reinterpret_cast<float2*>(&sW[r0 * 264 + c]) =
                    make_float2(acc[mt][nt][0], acc[mt][nt][1]);
                *reinterpret_cast<float2*>(&sW[(r0 + 8) * 264 + c]) =
                    make_float2(acc[mt][nt][2], acc[mt][nt][3]);
                u32 hi, lo;
                split2(acc[mt][nt][0], acc[mt][nt][1], hi, lo);
                size_t bi = (((size_t)batch * NN + n0 + r0) * 256 + c) >> 1;
                gwh[bi] = hi; gwl[bi] = lo;
                split2(acc[mt][nt][2], acc[mt][nt][3], hi, lo);
                bi = (((size_t)batch * NN + n0 + r0 + 8) * 256 + c) >> 1;
                gwh[bi] = hi; gwl[bi] = lo;
            }
    }
    __syncthreads();

    // partial accumulation: warp = (half, head); lane = slice g.
    {
        const int hh = w & 7;
        const int half = w >> 3;
        const int rbase = half * 32;
        float4 accT[8];
#pragma unroll
        for (int j = 0; j < 8; ++j) accT[j] = make_float4(0.f, 0.f, 0.f, 0.f);
        float accN = 0.f;
#pragma unroll 4
        for (int rr = 0; rr < 32; ++rr) {
            const int row = rbase + rr;
            const float wv = sW[row * 264 + hh * 32 + lane];
            accN += wv;
#pragma unroll
            for (int j = 0; j < 8; ++j) {
                const float4 f = *reinterpret_cast<const float4*>(
                    &sF[row * 264 + hh * 32 + j * 4]);
                accT[j].x = fmaf(wv, f.x, accT[j].x);
                accT[j].y = fmaf(wv, f.y, accT[j].y);
                accT[j].z = fmaf(wv, f.z, accT[j].z);
                accT[j].w = fmaf(wv, f.w, accT[j].w);
            }
        }
        const size_t pb = (size_t)blockIdx.x * 2 + half;
        float4* pt = reinterpret_cast<float4*>(
            g_part_tok + (pb * 256 + hh * 32 + lane) * DD);
#pragma unroll
        for (int j = 0; j < 8; ++j) pt[j] = accT[j];
        g_part_norm[pb * 256 + hh * 32 + lane] = accN;
    }
}

// ---------------- K2a: parallel partial reduce ---------------------------------
__global__ void __launch_bounds__(256)
k2a_reduce()
{
    __shared__ float red[8][33];
    __shared__ float rn[256];
    const int b  = blockIdx.x >> 8;
    const int hg = blockIdx.x & 255;
    const int tid = threadIdx.x;
    const int d = tid & 31, ck = tid >> 5;

    const float* base = g_part_tok + ((size_t)(b * PPB) * 256 + hg) * DD + d;
    float s = 0.f;
#pragma unroll 8
    for (int i = 0; i < PPB / 8; ++i)
        s += base[(size_t)(ck * (PPB / 8) + i) * (256 * DD)];
    red[ck][d] = s;

    float ns = 0.f;
#pragma unroll
    for (int j = 0; j < PPB / 256; ++j)
        ns += g_part_norm[(size_t)(b * PPB + tid * (PPB / 256) + j) * 256 + hg];
    rn[tid] = ns;
    __syncthreads();

    if (tid < 32) {
        float tot = 0.f;
#pragma unroll
        for (int c = 0; c < 8; ++c) tot += red[c][tid];
        g_tok_red[((size_t)b * 256 + hg) * DD + tid] = tot;
        float nsum = 0.f;
#pragma unroll
        for (int c = 0; c < 8; ++c) nsum += rn[tid + c * 32];
#pragma unroll
        for (int o = 16; o; o >>= 1) nsum += __shfl_xor_sync(0xffffffffu, nsum, o);
        if (tid == 0) g_norm_red[(size_t)b * 256 + hg] = nsum;
    }
}

// ---------------- K2b: attention + MLP + Wt frag images ------------------------
__global__ void __launch_bounds__(1024)
k2_tokens(const float* __restrict__ Wq, const float* __restrict__ Wk,
          const float* __restrict__ Wv,
          const float* __restrict__ tln_g, const float* __restrict__ tln_b,
          const float* __restrict__ W1, const float* __restrict__ b1,
          const float* __restrict__ W2, const float* __restrict__ b2,
          const float* __restrict__ Wo)
{
    const int b = blockIdx.x / HH;
    const int h = blockIdx.x % HH;
    const int tid = threadIdx.x;
    const int g = tid >> 5, d = tid & 31;

    __shared__ float s_st[GG][DD + 1];
    __shared__ float s_q[GG][DD + 1], s_k[GG][DD + 1], s_v[GG][DD + 1];
    __shared__ float s_attn[GG][GG + 1];
    __shared__ float s_h1[GG][4 * DD];
    __shared__ float s_tok2[GG][DD + 1];

    const float st = g_tok_red[((size_t)b * 256 + h * GG + g) * DD + d] /
                     (g_norm_red[(size_t)b * 256 + h * GG + g] + 1e-5f);
    s_st[g][d] = st;
    __syncthreads();

    float q = 0.f, kk = 0.f, vv = 0.f;
#pragma unroll
    for (int dd2 = 0; dd2 < DD; ++dd2) {
        const float sv = s_st[g][dd2];
        q  = fmaf(sv, Wq[dd2 * DD + d], q);
        kk = fmaf(sv, Wk[dd2 * DD + d], kk);
        vv = fmaf(sv, Wv[dd2 * DD + d], vv);
    }
    s_q[g][d] = q; s_k[g][d] = kk; s_v[g][d] = vv;
    __syncthreads();

    {
        const int kidx = d;
        float lg = 0.f;
#pragma unroll
        for (int dd2 = 0; dd2 < DD; ++dd2)
            lg = fmaf(s_q[g][dd2], s_k[kidx][dd2], lg);
        lg *= 0.17677669529663687f;
        float m = lg;
#pragma unroll
        for (int o = 16; o; o >>= 1) m = fmaxf(m, __shfl_xor_sync(0xffffffffu, m, o));
        const float e = __expf(lg - m);
        float ssum = e;
#pragma unroll
        for (int o = 16; o; o >>= 1) ssum += __shfl_xor_sync(0xffffffffu, ssum, o);
        s_attn[g][kidx] = e / ssum;
    }
    __syncthreads();

    float ot = st;
#pragma unroll
    for (int kidx = 0; kidx < GG; ++kidx)
        ot = fmaf(s_attn[g][kidx], s_v[kidx][d], ot);

    float s1 = ot, s2o = ot * ot;
#pragma unroll
    for (int o = 16; o; o >>= 1) {
        s1  += __shfl_xor_sync(0xffffffffu, s1,  o);
        s2o += __shfl_xor_sync(0xffffffffu, s2o, o);
    }
    const float mu = s1 * (1.f / DD);
    const float rstd = rsqrtf(s2o * (1.f / DD) - mu * mu + 1e-5f);
    const float hn = (ot - mu) * rstd * tln_g[d] + tln_b[d];
    __syncthreads();
    s_st[g][d] = hn;
    __syncthreads();

#pragma unroll
    for (int jj = 0; jj < 4; ++jj) {
        const int j = d + 32 * jj;
        float a = b1[j];
#pragma unroll
        for (int dd2 = 0; dd2 < DD; ++dd2)
            a = fmaf(s_st[g][dd2], W1[dd2 * (4 * DD) + j], a);
        a = 0.5f * a * (1.0f + erff(a * 0.70710678118654752f));
        s_h1[g][j] = a;
    }
    __syncthreads();

    float tk = b2[d];
#pragma unroll
    for (int j = 0; j < 4 * DD; ++j)
        tk = fmaf(s_h1[g][j], W2[j * DD + d], tk);
    tk += ot;
    s_tok2[g][d] = tk;
    __syncthreads();

    for (int idx = tid; idx < 4096; idx += 1024) {
        const int r = idx & 1;
        const int lane2 = (idx >> 1) & 31;
        const int nt = (idx >> 6) & 31;
        const int k16i = idx >> 11;
        const int t2 = lane2 & 3, g2 = lane2 >> 2;
        const int gl0 = k16i * 16 + r * 8 + 2 * t2;
        const int n = nt * 8 + g2;
        float v0 = 0.f, v1 = 0.f;
#pragma unroll
        for (int dd2 = 0; dd2 < DD; ++dd2) {
            const float wov = Wo[(h * DD + dd2) * CC + n];
            v0 = fmaf(s_tok2[gl0][dd2], wov, v0);
            v1 = fmaf(s_tok2[gl0 + 1][dd2], wov, v1);
        }
        u32 hi, lo;
        split2(v0, v1, hi, lo);
        const size_t oi = (size_t)b * 32768 +
            ((((size_t)(h * 2 + k16i) * 32 + nt) * 32 + lane2) * 2 + r);
        g_Wt_hi[oi] = hi;
        g_Wt_lo[oi] = lo;
    }
}

// ---------------- K3: out = w @ Wt + bo + LN(fx), smem-staged B ----------------
// Pass order per ch: stage Bh -> (Ah x Bh), (Al x Bh) -> stage Bl -> (Ah x Bl).
#define S3_ALO   67584
#define S3_B     135168
#define S3_MU    (S3_B + 65536)       // 200704
#define S3_RS    (S3_MU + 512)
#define S3_TOTAL (S3_RS + 512)

__global__ void __launch_bounds__(512, 1)
k3_tc(const float* __restrict__ fx,
      const float* __restrict__ ln_g, const float* __restrict__ ln_b,
      const float* __restrict__ bo,  float* __restrict__ out)
{
    extern __shared__ char smem[];
    u32*   sAh = reinterpret_cast<u32*>(smem);
    u32*   sAl = reinterpret_cast<u32*>(smem + S3_ALO);
    uint2* sB  = reinterpret_cast<uint2*>(smem + S3_B);
    float* sMu = reinterpret_cast<float*>(smem + S3_MU);
    float* sRs = reinterpret_cast<float*>(smem + S3_RS);

    const int tid  = threadIdx.x;
    const int w    = tid >> 5;
    const int lane = tid & 31;
    const int g    = lane >> 2, t = lane & 3;
    const int wr   = w >> 2;
    const int wn   = w & 3;
    const int batch = blockIdx.x / BLKS3;
    const int n0    = (blockIdx.x % BLKS3) * TOK3;

    {
        const u32* gwh = reinterpret_cast<const u32*>(g_w_hi) +
                         (((size_t)batch * NN + n0) * 256 >> 1);
        const u32* gwl = reinterpret_cast<const u32*>(g_w_lo) +
                         (((size_t)batch * NN + n0) * 256 >> 1);
        for (int idx = tid; idx < 128 * 128; idx += 512) {
            const int row = idx >> 7, cp = idx & 127;
            sAh[row * 132 + cp] = gwh[row * 128 + cp];
            sAl[row * 132 + cp] = gwl[row * 128 + cp];
        }
    }

    for (int i = 0; i < 8; ++i) {
        const int row = w * 8 + i;
        const float* rp = fx + ((size_t)batch * NN + n0 + row) * CC + lane * 8;
        const float4 f1 = *reinterpret_cast<const float4*>(rp);
        const float4 f2 = *reinterpret_cast<const float4*>(rp + 4);
        float s = f1.x + f1.y + f1.z + f1.w + f2.x + f2.y + f2.z + f2.w;
        float s2 = f1.x * f1.x + f1.y * f1.y + f1.z * f1.z + f1.w * f1.w +
                   f2.x * f2.x + f2.y * f2.y + f2.z * f2.z + f2.w * f2.w;
#pragma unroll
        for (int o = 16; o; o >>= 1) {
            s  += __shfl_xor_sync(0xffffffffu, s,  o);
            s2 += __shfl_xor_sync(0xffffffffu, s2, o);
        }
        if (lane == 0) {
            const float mu = s * (1.f / CC);
            sMu[row] = mu;
            sRs[row] = rsqrtf(s2 * (1.f / CC) - mu * mu + 1e-5f);
        }
    }

    const uint2* BhG = reinterpret_cast<const uint2*>(g_Wt_hi + (size_t)batch * 32768);
    const uint2* BlG = reinterpret_cast<const uint2*>(g_Wt_lo + (size_t)batch * 32768);

#pragma unroll 1
    for (int ch = 0; ch < 2; ++ch) {
        float acc[2][4][4];
#pragma unroll
        for (int mt = 0; mt < 2; ++mt)
#pragma unroll
            for (int nt = 0; nt < 4; ++nt)
#pragma unroll
                for (int i = 0; i < 4; ++i) acc[mt][nt][i] = 0.f;

        // seg 0: stage Bh, A=Ah; seg 1: no stage, A=Al; seg 2: stage Bl, A=Ah
#pragma unroll 1
        for (int seg = 0; seg < 3; ++seg) {
            if (seg != 1) {
                const uint2* Bsrc = (seg == 0) ? BhG : BlG;
                __syncthreads();
#pragma unroll
                for (int i = 0; i < 16; ++i) {
                    const int o = tid + i * 512;               // 0..8191
                    const int k16s = o >> 9;
                    sB[o] = Bsrc[o + k16s * 512 + ch * 512];
                }
                __syncthreads();
            }
            const u32* A = (seg == 1) ? sAl : sAh;
#pragma unroll 1
            for (int k16 = 0; k16 < 16; ++k16) {
                u32 a[2][4];
#pragma unroll
                for (int mt = 0; mt < 2; ++mt) {
                    const int wi = (wr * 32 + mt * 16 + g) * 132 + k16 * 8 + t;
                    a[mt][0] = A[wi];
                    a[mt][1] = A[wi + 8 * 132];
                    a[mt][2] = A[wi + 4];
                    a[mt][3] = A[wi + 8 * 132 + 4];
                }
                uint2 b[4];
#pragma unroll
                for (int nt = 0; nt < 4; ++nt)
                    b[nt] = sB[k16 * 512 + (wn * 4 + nt) * 32 + lane];
#pragma unroll
                for (int mt = 0; mt < 2; ++mt)
#pragma unroll
                    for (int nt = 0; nt < 4; ++nt)
                        mma16816(acc[mt][nt], a[mt], b[nt].x, b[nt].y);
            }
        }

        // epilogue for this ch
#pragma unroll
        for (int mt = 0; mt < 2; ++mt)
#pragma unroll
            for (int nt = 0; nt < 4; ++nt) {
                const int c = ch * 128 + wn * 32 + nt * 8 + 2 * t;
                const float bo0 = bo[c], bo1 = bo[c + 1];
                const float lg0 = ln_g[c], lg1 = ln_g[c + 1];
                const float lb0 = ln_b[c], lb1 = ln_b[c + 1];
#pragma unroll
                for (int rv = 0; rv < 2; ++rv) {
                    const int row = wr * 32 + mt * 16 + g + rv * 8;
                    const size_t go = ((size_t)batch * NN + n0 + row) * 256 + c;
                    const float2 fv = *reinterpret_cast<const float2*>(&fx[go]);
                    const float mu = sMu[row], rs = sRs[row];
                    float2 o;
                    o.x = acc[mt][nt][rv * 2]     + bo0 + (fv.x - mu) * rs * lg0 + lb0;
                    o.y = acc[mt][nt][rv * 2 + 1] + bo1 + (fv.y - mu) * rs * lg1 + lb1;
                    *reinterpret_cast<float2*>(&out[go]) = o;
                }
            }
    }
}

// ---------------- launch -------------------------------------------------------
extern "C" void kernel_launch(void* const* d_in, const int* in_sizes, int n_in,
                              void* d_out, int out_size)
{
    const float* fx    = (const float*)d_in[0];
    const float* ln_g  = (const float*)d_in[1];
    const float* ln_b  = (const float*)d_in[2];
    const float* Wx    = (const float*)d_in[3];
    const float* bx    = (const float*)d_in[4];
    const float* Wfx   = (const float*)d_in[5];
    const float* bfx   = (const float*)d_in[6];
    const float* Ws    = (const float*)d_in[7];
    const float* bs    = (const float*)d_in[8];
    const float* tempp = (const float*)d_in[9];
    const float* Wq    = (const float*)d_in[10];
    const float* Wk    = (const float*)d_in[11];
    const float* Wv    = (const float*)d_in[12];
    const float* tln_g = (const float*)d_in[13];
    const float* tln_b = (const float*)d_in[14];
    const float* W1    = (const float*)d_in[15];
    const float* b1    = (const float*)d_in[16];
    const float* W2    = (const float*)d_in[17];
    const float* b2    = (const float*)d_in[18];
    const float* Wo    = (const float*)d_in[19];
    const float* bo    = (const float*)d_in[20];
    float* out = (float*)d_out;

    static int s_init = 0;
    if (!s_init) {
        cudaFuncSetAttribute(k1_dispatch, cudaFuncAttributeMaxDynamicSharedMemorySize, S1_TOTAL);
        cudaFuncSetAttribute(k3_tc, cudaFuncAttributeMaxDynamicSharedMemorySize, S3_TOTAL);
        s_init = 1;
    }

    k0_pack<<<256, 256>>>(Wx, Ws, bs, bx, Wfx);
    k1_dispatch<<<NBLK1, 512, S1_TOTAL>>>(fx, ln_g, ln_b, bfx, tempp);
    k2a_reduce<<<BB * 256, 256>>>();
    k2_tokens<<<BB * HH, 1024>>>(Wq, Wk, Wv, tln_g, tln_b, W1, b1, W2, b2, Wo);
    k3_tc<<<NBLK3, 512, S3_TOTAL>>>(fx, ln_g, ln_b, bo, out);
}